// round 14
// baseline (speedup 1.0000x reference)
#include <cuda_runtime.h>
#include <cuda_fp16.h>
#include <cstdint>
#include <math.h>

// Problem constants
#define BATCH 2
#define SEQ   2048
#define EMB   1024
#define HEADS 16
#define HDIM  64
#define MROWS (BATCH * SEQ)   // 4096

// ---------------- scratch (device globals; no allocations allowed) ---------
__device__ __half g_Q[MROWS * EMB];     // Q proj: scaled, rounded, plain [token][dim]
__device__ __half g_K[MROWS * EMB];     // K proj: rounded, plain
__device__ __half g_V[MROWS * EMB];     // V proj: rounded, plain
__device__ __half g_C[MROWS * EMB];     // attention out: rounded, plain
__device__ __half g_WT[4][EMB * EMB];   // W^T: rounded, plain [n][k]
__device__ __half g_X[3][MROWS * EMB];  // xq/xk/xv: rounded, plain

#define QSCALE 0.18033688f   // 0.125 * log2(e)

// ============================================================================
// helpers
// ============================================================================
__device__ __forceinline__ uint32_t smem_u32(const void* p) {
    uint32_t a;
    asm("{ .reg .u64 t; cvta.to.shared.u64 t, %1; cvt.u32.u64 %0, t; }"
        : "=r"(a) : "l"(p));
    return a;
}

// pack two f32 -> f16x2 (lo = first arg)
__device__ __forceinline__ uint32_t h2pack(float lo, float hi) {
    uint32_t r;
    asm("cvt.rn.f16x2.f32 %0, %1, %2;" : "=r"(r) : "f"(hi), "f"(lo));
    return r;
}

__device__ __forceinline__ float ex2(float x) {
    float r;
    asm("ex2.approx.f32 %0, %1;" : "=f"(r) : "f"(x));
    return r;
}

#define MMA_F16(c, a, b)                                                      \
    asm volatile("mma.sync.aligned.m16n8k16.row.col.f32.f16.f16.f32 "         \
                 "{%0,%1,%2,%3}, {%4,%5,%6,%7}, {%8,%9}, {%0,%1,%2,%3};"      \
                 : "+f"((c)[0]), "+f"((c)[1]), "+f"((c)[2]), "+f"((c)[3])     \
                 : "r"((a)[0]), "r"((a)[1]), "r"((a)[2]), "r"((a)[3]),        \
                   "r"((b)[0]), "r"((b)[1]))

#define LDSM_X4(r0, r1, r2, r3, addr)                                         \
    asm volatile("ldmatrix.sync.aligned.m8n8.x4.shared.b16 "                  \
                 "{%0,%1,%2,%3}, [%4];"                                       \
                 : "=r"(r0), "=r"(r1), "=r"(r2), "=r"(r3) : "r"(addr))

#define LDSM_X4_T(r0, r1, r2, r3, addr)                                       \
    asm volatile("ldmatrix.sync.aligned.m8n8.x4.trans.shared.b16 "            \
                 "{%0,%1,%2,%3}, [%4];"                                       \
                 : "=r"(r0), "=r"(r1), "=r"(r2), "=r"(r3) : "r"(addr))

#define CP_ASYNC16(dst, src)                                                  \
    asm volatile("cp.async.cg.shared.global [%0], [%1], 16;"                  \
                 :: "r"(dst), "l"(src))
#define CP_COMMIT() asm volatile("cp.async.commit_group;" ::: "memory")
#define CP_WAIT0()  asm volatile("cp.async.wait_group 0;" ::: "memory")

// ============================================================================
// Merged prep: z<3 -> activation convert (xq/xk/xv), z>=3 -> weight transpose.
// grid (32, 32, 7), block 256.
// ============================================================================
__global__ void __launch_bounds__(256)
prep_kernel(const float* __restrict__ xq, const float* __restrict__ xk,
            const float* __restrict__ xv,
            const float* __restrict__ Wq, const float* __restrict__ Wk,
            const float* __restrict__ Wv, const float* __restrict__ Wo,
            __half* __restrict__ Xbase, __half* __restrict__ WTbase)
{
    const int z = blockIdx.z;
    const int tid = threadIdx.x;

    if (z < 3) {
        const float* X = (z == 0) ? xq : (z == 1) ? xk : xv;
        __half* Y = Xbase + (size_t)z * MROWS * EMB;
        size_t blk = (size_t)blockIdx.y * 32 + blockIdx.x;   // 0..1023
        size_t i16 = blk * 256 + tid;
        const float* xp = X + i16 * 16;
        uint32_t* yp = (uint32_t*)Y + i16 * 8;
        uint32_t o[8];
#pragma unroll
        for (int q = 0; q < 4; ++q) {
            float4 v = *(const float4*)&xp[q * 4];
            o[q * 2 + 0] = h2pack(v.x, v.y);
            o[q * 2 + 1] = h2pack(v.z, v.w);
        }
        uint4 w0 = { o[0], o[1], o[2], o[3] };
        uint4 w1 = { o[4], o[5], o[6], o[7] };
        *(uint4*)&yp[0] = w0;
        *(uint4*)&yp[4] = w1;
    } else {
        const int wz = z - 3;
        const float* W = (wz == 0) ? Wq : (wz == 1) ? Wk : (wz == 2) ? Wv : Wo;
        __half* WT = WTbase + (size_t)wz * EMB * EMB;

        __shared__ float tile[32][33];
        const int tx = tid & 31;
        const int ty = tid >> 5;
        int x = blockIdx.x * 32 + tx;   // n
        int y = blockIdx.y * 32 + ty;   // k
#pragma unroll
        for (int j = 0; j < 32; j += 8)
            tile[ty + j][tx] = W[(size_t)(y + j) * EMB + x];
        __syncthreads();
        const int cu = tx & 15;                 // k-pair within 32-k block
        const int nl0 = ty + 8 * (tx >> 4);
        uint32_t* Wu = (uint32_t*)WT;
#pragma unroll
        for (int j = 0; j < 32; j += 16) {
            int nl = nl0 + j;
            uint32_t h = h2pack(tile[2 * cu][nl], tile[2 * cu + 1][nl]);
            size_t n = (size_t)(blockIdx.x * 32 + nl);
            Wu[n * (EMB / 2) + blockIdx.y * 16 + cu] = h;
        }
    }
}

// ============================================================================
// fp16 mma.sync GEMM mainloop, ldmatrix staging, plain layouts.
// Tile 128x128, BK=64 halves, stride 36 u32 (LDSM conflict-free).
// ============================================================================
#define GBM 128
#define GBN 128
#define GRS 36                       // u32 per row (32 data + 4 pad)
#define TILE_U (128 * GRS)
#define GSMEM_TOTAL (4 * TILE_U * 4) // 73,728 B

struct GemmCtx {
    int wm, wn, g, t;
    float c[4][4][4];
};

__device__ __forceinline__ void gemm_mainloop(
    const __half* __restrict__ Ap, const __half* __restrict__ Bp,
    uint32_t sb, int tid, GemmCtx& ctx)
{
    const int w    = tid >> 5;
    ctx.wm = w & 1;
    ctx.wn = w >> 1;
    const int lane = tid & 31;
    ctx.g = lane >> 2;
    ctx.t = lane & 3;

    const int s  = tid & 7;
    const int r0 = tid >> 3;

    const uint32_t AsU[2] = { sb,                  sb + TILE_U * 4 };
    const uint32_t BsU[2] = { sb + 2 * TILE_U * 4, sb + 3 * TILE_U * 4 };

#pragma unroll
    for (int mi = 0; mi < 4; ++mi)
#pragma unroll
        for (int ni = 0; ni < 4; ++ni)
#pragma unroll
            for (int j = 0; j < 4; ++j) ctx.c[mi][ni][j] = 0.f;

    // ldmatrix lane bases (verified mappings from attention kernel)
    const int laneRowA = ((lane & 8) ? 8 : 0) + (lane & 7);
    const int colOctA  = (lane >> 4) * 4;
    const int laneRowB = ((lane >> 4) << 3) + (lane & 7);
    const int colOctB  = (lane & 8) ? 4 : 0;

    const uint32_t dOff = (uint32_t)((r0 * GRS + s * 4) * 4);
    const size_t   gOff = (size_t)r0 * EMB + s * 8;   // halves

    {
#pragma unroll
        for (int p = 0; p < 4; ++p) {
            CP_ASYNC16(AsU[0] + dOff + (uint32_t)(32 * p * GRS * 4),
                       Ap + gOff + (size_t)32 * p * EMB);
            CP_ASYNC16(BsU[0] + dOff + (uint32_t)(32 * p * GRS * 4),
                       Bp + gOff + (size_t)32 * p * EMB);
        }
        CP_COMMIT();
    }

    const int NKT = EMB / 64;   // 16
    for (int kt = 0; kt < NKT; ++kt) {
        const int b = kt & 1;

        if (kt + 1 < NKT) {
            const int nb = b ^ 1;
            const size_t k0 = (size_t)(kt + 1) * 64;   // halves
#pragma unroll
            for (int p = 0; p < 4; ++p) {
                CP_ASYNC16(AsU[nb] + dOff + (uint32_t)(32 * p * GRS * 4),
                           Ap + gOff + k0 + (size_t)32 * p * EMB);
                CP_ASYNC16(BsU[nb] + dOff + (uint32_t)(32 * p * GRS * 4),
                           Bp + gOff + k0 + (size_t)32 * p * EMB);
            }
            CP_COMMIT();
            asm volatile("cp.async.wait_group 1;" ::: "memory");
        } else {
            CP_WAIT0();
        }
        __syncthreads();

        const uint32_t aU = AsU[b];
        const uint32_t bU = BsU[b];
#pragma unroll
        for (int ks = 0; ks < 4; ++ks) {       // each kstep = 16 halves
            uint32_t af[4][4], bf[4][2];
#pragma unroll
            for (int mi = 0; mi < 4; ++mi) {
                LDSM_X4(af[mi][0], af[mi][1], af[mi][2], af[mi][3],
                        aU + (uint32_t)(((ctx.wm * 64 + mi * 16 + laneRowA) * GRS
                                         + ks * 8 + colOctA) * 4));
            }
#pragma unroll
            for (int kb = 0; kb < 2; ++kb) {
                uint32_t r0v, r1v, r2v, r3v;
                LDSM_X4(r0v, r1v, r2v, r3v,
                        bU + (uint32_t)(((ctx.wn * 32 + kb * 16 + laneRowB) * GRS
                                         + ks * 8 + colOctB) * 4));
                bf[2 * kb][0] = r0v; bf[2 * kb][1] = r1v;
                bf[2 * kb + 1][0] = r2v; bf[2 * kb + 1][1] = r3v;
            }
#pragma unroll
            for (int mi = 0; mi < 4; ++mi)
#pragma unroll
                for (int ni = 0; ni < 4; ++ni)
                    MMA_F16(ctx.c[mi][ni], af[mi], bf[ni]);
        }
        __syncthreads();
    }
}

// ============================================================================
// Merged QKV GEMM: outputs plain [token][dim] half (Q scaled by QSCALE).
// ============================================================================
__global__ void __launch_bounds__(256, 2)
gemm_qkv_kernel(const __half* __restrict__ Xbase, const __half* __restrict__ WTbase,
                const float* __restrict__ bq, const float* __restrict__ bk,
                const float* __restrict__ bv,
                __half* __restrict__ Qd, __half* __restrict__ Kd,
                __half* __restrict__ Vd)
{
    extern __shared__ uint32_t smu[];
    const uint32_t sb = smem_u32(smu);
    const int tid = threadIdx.x;
    const int bn = blockIdx.x * GBN;
    const int bm = blockIdx.y * GBM;
    const int z  = blockIdx.z;

    const __half* A  = Xbase  + (size_t)z * MROWS * EMB + (size_t)bm * EMB;
    const __half* Bw = WTbase + (size_t)z * EMB * EMB   + (size_t)bn * EMB;
    const float* bias = (z == 0) ? bq : (z == 1) ? bk : bv;
    __half* outp = (z == 0) ? Qd : (z == 1) ? Kd : Vd;

    GemmCtx ctx;
    gemm_mainloop(A, Bw, sb, tid, ctx);

    const int colb = bn + ctx.wn * 32;
    const int g = ctx.g, t = ctx.t;
    const float sc = (z == 0) ? QSCALE : 1.f;
    float2 bj[4];
#pragma unroll
    for (int ni = 0; ni < 4; ++ni) {
        bj[ni].x = bias[colb + ni * 8 + 2 * t];
        bj[ni].y = bias[colb + ni * 8 + 2 * t + 1];
    }

    uint32_t* Cu = (uint32_t*)outp;
#pragma unroll
    for (int mi = 0; mi < 4; ++mi) {
        const size_t row0 = (size_t)(bm + ctx.wm * 64 + mi * 16 + g);
        const size_t row1 = row0 + 8;
#pragma unroll
        for (int ni = 0; ni < 4; ++ni) {
            const int posu = (colb >> 1) + ni * 4 + t;
            Cu[row0 * (EMB / 2) + posu] =
                h2pack((ctx.c[mi][ni][0] + bj[ni].x) * sc,
                       (ctx.c[mi][ni][1] + bj[ni].y) * sc);
            Cu[row1 * (EMB / 2) + posu] =
                h2pack((ctx.c[mi][ni][2] + bj[ni].x) * sc,
                       (ctx.c[mi][ni][3] + bj[ni].y) * sc);
        }
    }
}

// ============================================================================
// Final projection GEMM: fp32 row-major output.
// ============================================================================
__global__ void __launch_bounds__(256, 2)
gemm_out_kernel(const __half* __restrict__ A, const __half* __restrict__ WT,
                const float* __restrict__ bias, float* __restrict__ C)
{
    extern __shared__ uint32_t smu[];
    const uint32_t sb = smem_u32(smu);
    const int tid = threadIdx.x;
    const int bn = blockIdx.x * GBN;
    const int bm = blockIdx.y * GBM;

    GemmCtx ctx;
    gemm_mainloop(A + (size_t)bm * EMB, WT + (size_t)bn * EMB, sb, tid, ctx);

    const int colb = bn + ctx.wn * 32;
    const int g = ctx.g, t = ctx.t;
    float2 bj[4];
#pragma unroll
    for (int ni = 0; ni < 4; ++ni) {
        bj[ni].x = bias[colb + ni * 8 + 2 * t];
        bj[ni].y = bias[colb + ni * 8 + 2 * t + 1];
    }
#pragma unroll
    for (int mi = 0; mi < 4; ++mi) {
        const size_t row0 = (size_t)(bm + ctx.wm * 64 + mi * 16 + g);
        const size_t row1 = row0 + 8;
#pragma unroll
        for (int ni = 0; ni < 4; ++ni) {
            const int col = colb + ni * 8 + 2 * t;
            float2 o0, o1;
            o0.x = ctx.c[mi][ni][0] + bj[ni].x;
            o0.y = ctx.c[mi][ni][1] + bj[ni].y;
            o1.x = ctx.c[mi][ni][2] + bj[ni].x;
            o1.y = ctx.c[mi][ni][3] + bj[ni].y;
            *(float2*)&C[row0 * EMB + col] = o0;
            *(float2*)&C[row1 * EMB + col] = o1;
        }
    }
}

// ============================================================================
// Flash attention (R13 structure; epilogue now plain layout).
// ============================================================================
#define RS 36
#define AOFF_Q 0                              // [128][RS]
#define AOFF_K (128 * RS)                     // 2 x [64][RS]
#define AOFF_V (AOFF_K + 2 * 64 * RS)         // 2 x [64][RS]
#define ATT_SMEM ((AOFF_V + 2 * 64 * RS) * 4) // 55,296 B -> 2 CTAs/SM

__global__ void __launch_bounds__(256, 2)
attn_mma_kernel(const __half* __restrict__ Q, const __half* __restrict__ K,
                const __half* __restrict__ V, __half* __restrict__ O)
{
    extern __shared__ uint32_t smu[];
    const uint32_t sb = smem_u32(smu);

    const uint32_t QsU = sb + AOFF_Q * 4;
    const uint32_t KsU[2] = { sb + AOFF_K * 4, sb + (AOFF_K + 64 * RS) * 4 };
    const uint32_t VsU[2] = { sb + AOFF_V * 4, sb + (AOFF_V + 64 * RS) * 4 };

    const int tid = threadIdx.x;
    const int qt = blockIdx.x;           // 0..15
    const int bh = blockIdx.y;           // 0..31
    const int b  = bh >> 4;
    const int hd = bh & 15;
    const int q0 = qt * 128;

    const __half* Qg = Q + (size_t)(b * SEQ + q0) * EMB + hd * HDIM;
    const __half* Kg = K + (size_t)b * SEQ * EMB + hd * HDIM;
    const __half* Vg = V + (size_t)b * SEQ * EMB + hd * HDIM;

    const int w    = tid >> 5;      // 0..7 : q-rows 16w..16w+15
    const int lane = tid & 31;
    const int g    = lane >> 2;
    const int t    = lane & 3;
    const int rowg = 16 * w + g;

    const int cq = tid & 7;
    const int rr = tid >> 3;

    // ---- stage Q (128 rows), K0/V0 via cp.async ----
#pragma unroll
    for (int p = 0; p < 4; ++p) {
        int r = rr + 32 * p;
        CP_ASYNC16(QsU + (uint32_t)((r * RS + cq * 4) * 4),
                   Qg + (size_t)r * EMB + cq * 8);
    }
#pragma unroll
    for (int p = 0; p < 2; ++p) {
        int r = rr + 32 * p;
        CP_ASYNC16(KsU[0] + (uint32_t)((r * RS + cq * 4) * 4),
                   Kg + (size_t)r * EMB + cq * 8);
        CP_ASYNC16(VsU[0] + (uint32_t)((r * RS + cq * 4) * 4),
                   Vg + (size_t)r * EMB + cq * 8);
    }
    CP_COMMIT();
    CP_WAIT0();
    __syncthreads();

    // ---- hoist Q a-frags via ldmatrix x4 ----
    uint32_t qf[4][4];
    {
        const int laneRowA = ((lane & 8) ? 8 : 0) + (lane & 7);
        const int colOctA  = (lane >> 4) * 4;
        const uint32_t qbase = QsU
            + (uint32_t)(((w * 16 + laneRowA) * RS + colOctA) * 4);
#pragma unroll
        for (int ks = 0; ks < 4; ++ks)
            LDSM_X4(qf[ks][0], qf[ks][1], qf[ks][2], qf[ks][3],
                    qbase + (uint32_t)(ks * 8 * 4));
    }

    float o[8][4];
#pragma unroll
    for (int ni = 0; ni < 8; ++ni)
#pragma unroll
        for (int j = 0; j < 4; ++j) o[ni][j] = 0.f;
    float lp0 = 0.f, lp1 = 0.f;

    const int laneRowB = ((lane >> 4) << 3) + (lane & 7);
    const int colOctB  = (lane & 8) ? 4 : 0;
    const uint32_t vlane = (uint32_t)(((lane & 15) * RS + 4 * (lane >> 4)) * 4);

    const int NT = SEQ / 64;   // 32
    for (int kt = 0; kt < NT; ++kt) {
        const int cur = kt & 1;

        CP_WAIT0();
        __syncthreads();

        if (kt + 1 < NT) {
            const int nxt = cur ^ 1;
            const int k0n = (kt + 1) * 64;
#pragma unroll
            for (int p = 0; p < 2; ++p) {
                int r = rr + 32 * p;
                CP_ASYNC16(KsU[nxt] + (uint32_t)((r * RS + cq * 4) * 4),
                           Kg + (size_t)(k0n + r) * EMB + cq * 8);
                CP_ASYNC16(VsU[nxt] + (uint32_t)((r * RS + cq * 4) * 4),
                           Vg + (size_t)(k0n + r) * EMB + cq * 8);
            }
            CP_COMMIT();
        }

        // ---- S = Q @ K^T ----
        float s[8][4];
#pragma unroll
        for (int ni = 0; ni < 8; ++ni)
#pragma unroll
            for (int j = 0; j < 4; ++j) s[ni][j] = 0.f;

#pragma unroll
        for (int ks = 0; ks < 4; ++ks) {
#pragma unroll
            for (int kb = 0; kb < 4; ++kb) {
                uint32_t r0, r1, r2, r3;
                uint32_t a = KsU[cur]
                    + (uint32_t)(((kb * 16 + laneRowB) * RS
                                  + ks * 8 + colOctB) * 4);
                LDSM_X4(r0, r1, r2, r3, a);
                uint32_t b0[2] = { r0, r1 };
                uint32_t b1[2] = { r2, r3 };
                MMA_F16(s[2 * kb],     qf[ks], b0);
                MMA_F16(s[2 * kb + 1], qf[ks], b1);
            }
        }

        // ---- p = exp2(s) -> PV a-frags in registers ----
        uint32_t pf[4][4];
#pragma unroll
        for (int ks = 0; ks < 4; ++ks) {
            float e00 = ex2(s[2 * ks][0]);
            float e01 = ex2(s[2 * ks][1]);
            float e02 = ex2(s[2 * ks][2]);
            float e03 = ex2(s[2 * ks][3]);
            float e10 = ex2(s[2 * ks + 1][0]);
            float e11 = ex2(s[2 * ks + 1][1]);
            float e12 = ex2(s[2 * ks + 1][2]);
            float e13 = ex2(s[2 * ks + 1][3]);
            lp0 += e00 + e01 + e10 + e11;
            lp1 += e02 + e03 + e12 + e13;
            pf[ks][0] = h2pack(e00, e01);
            pf[ks][1] = h2pack(e02, e03);
            pf[ks][2] = h2pack(e10, e11);
            pf[ks][3] = h2pack(e12, e13);
        }

        // ---- O += P @ V ----
#pragma unroll
        for (int ks = 0; ks < 4; ++ks) {
            const uint32_t vrow = VsU[cur] + vlane
                                + (uint32_t)(ks * 16 * RS * 4);
#pragma unroll
            for (int d16 = 0; d16 < 4; ++d16) {
                uint32_t r0, r1, r2, r3;
                LDSM_X4_T(r0, r1, r2, r3, vrow + (uint32_t)(d16 * 8 * 4));
                uint32_t b0[2] = { r0, r1 };
                uint32_t b1[2] = { r2, r3 };
                MMA_F16(o[2 * d16],     pf[ks], b0);
                MMA_F16(o[2 * d16 + 1], pf[ks], b1);
            }
        }
    }

    // ---- reduce l, normalize, store plain half2 ----
    lp0 += __shfl_xor_sync(0xffffffffu, lp0, 1);
    lp0 += __shfl_xor_sync(0xffffffffu, lp0, 2);
    lp1 += __shfl_xor_sync(0xffffffffu, lp1, 1);
    lp1 += __shfl_xor_sync(0xffffffffu, lp1, 2);
    const float inv0 = 1.f / lp0;
    const float inv1 = 1.f / lp1;

    uint32_t* Ou = (uint32_t*)O;
    const size_t tok0 = (size_t)(b * SEQ + q0 + rowg);
    const size_t tok1 = tok0 + 8;
#pragma unroll
    for (int ni = 0; ni < 8; ++ni) {
        const int posu = hd * 32 + ni * 4 + t;   // plain: dim (ni*8 + 2t)/2
        Ou[tok0 * (EMB / 2) + posu] = h2pack(o[ni][0] * inv0, o[ni][1] * inv0);
        Ou[tok1 * (EMB / 2) + posu] = h2pack(o[ni][2] * inv1, o[ni][3] * inv1);
    }
}

// ============================================================================
// launch
// ============================================================================
extern "C" void kernel_launch(void* const* d_in, const int* in_sizes, int n_in,
                              void* d_out, int out_size)
{
    const float* xv = (const float*)d_in[0];
    const float* xk = (const float*)d_in[1];
    const float* xq = (const float*)d_in[2];
    const float* Wq = (const float*)d_in[3];
    const float* bq = (const float*)d_in[4];
    const float* Wk = (const float*)d_in[5];
    const float* bk = (const float*)d_in[6];
    const float* Wv = (const float*)d_in[7];
    const float* bv = (const float*)d_in[8];
    const float* Wo = (const float*)d_in[9];
    const float* bo = (const float*)d_in[10];
    float* out = (float*)d_out;

    __half *Qd, *Kd, *Vd, *Cd, *WTd, *Xd;
    cudaGetSymbolAddress((void**)&Qd, g_Q);
    cudaGetSymbolAddress((void**)&Kd, g_K);
    cudaGetSymbolAddress((void**)&Vd, g_V);
    cudaGetSymbolAddress((void**)&Cd, g_C);
    cudaGetSymbolAddress((void**)&WTd, g_WT);
    cudaGetSymbolAddress((void**)&Xd, g_X);

    __half* WoT = WTd + 3ll * EMB * EMB;

    // merged prep: activations (z 0-2) + weight transposes (z 3-6)
    dim3 pgrid(32, 32, 7);
    prep_kernel<<<pgrid, 256>>>(xq, xk, xv, Wq, Wk, Wv, Wo, Xd, WTd);

    cudaFuncSetAttribute(gemm_qkv_kernel,
                         cudaFuncAttributeMaxDynamicSharedMemorySize, GSMEM_TOTAL);
    cudaFuncSetAttribute(gemm_out_kernel,
                         cudaFuncAttributeMaxDynamicSharedMemorySize, GSMEM_TOTAL);

    dim3 qkvgrid(EMB / GBN, MROWS / GBM, 3);   // (8, 32, 3)
    gemm_qkv_kernel<<<qkvgrid, 256, GSMEM_TOTAL>>>(Xd, WTd, bq, bk, bv,
                                                   Qd, Kd, Vd);

    cudaFuncSetAttribute(attn_mma_kernel,
                         cudaFuncAttributeMaxDynamicSharedMemorySize, ATT_SMEM);
    dim3 agrid(SEQ / 128, BATCH * HEADS);  // (16, 32)
    attn_mma_kernel<<<agrid, 256, ATT_SMEM>>>(Qd, Kd, Vd, Cd);

    dim3 ggrid(EMB / GBN, MROWS / GBM);   // (8, 32)
    gemm_out_kernel<<<ggrid, 256, GSMEM_TOTAL>>>(Cd, WoT, bo, out);
}

// round 15
// speedup vs baseline: 1.0001x; 1.0001x over previous
#include <cuda_runtime.h>
#include <cuda_fp16.h>
#include <cstdint>
#include <math.h>

// Problem constants
#define BATCH 2
#define SEQ   2048
#define EMB   1024
#define HEADS 16
#define HDIM  64
#define MROWS (BATCH * SEQ)   // 4096

// ---------------- scratch (device globals; no allocations allowed) ---------
__device__ __half g_Q[MROWS * EMB];     // Q proj: scaled, rounded, plain [token][dim]
__device__ __half g_K[MROWS * EMB];     // K proj: rounded, plain
__device__ __half g_V[MROWS * EMB];     // V proj: rounded, plain
__device__ __half g_C[MROWS * EMB];     // attention out: rounded, plain
__device__ __half g_WT[4][EMB * EMB];   // W^T: rounded, plain [n][k]
__device__ __half g_X[3][MROWS * EMB];  // xq/xk/xv: rounded, plain

#define QSCALE 0.18033688f   // 0.125 * log2(e)

// ============================================================================
// helpers
// ============================================================================
__device__ __forceinline__ uint32_t smem_u32(const void* p) {
    uint32_t a;
    asm("{ .reg .u64 t; cvta.to.shared.u64 t, %1; cvt.u32.u64 %0, t; }"
        : "=r"(a) : "l"(p));
    return a;
}

__device__ __forceinline__ uint32_t h2pack(float lo, float hi) {
    uint32_t r;
    asm("cvt.rn.f16x2.f32 %0, %1, %2;" : "=r"(r) : "f"(hi), "f"(lo));
    return r;
}

__device__ __forceinline__ float ex2(float x) {
    float r;
    asm("ex2.approx.f32 %0, %1;" : "=f"(r) : "f"(x));
    return r;
}

#define MMA_F16(c, a, b)                                                      \
    asm volatile("mma.sync.aligned.m16n8k16.row.col.f32.f16.f16.f32 "         \
                 "{%0,%1,%2,%3}, {%4,%5,%6,%7}, {%8,%9}, {%0,%1,%2,%3};"      \
                 : "+f"((c)[0]), "+f"((c)[1]), "+f"((c)[2]), "+f"((c)[3])     \
                 : "r"((a)[0]), "r"((a)[1]), "r"((a)[2]), "r"((a)[3]),        \
                   "r"((b)[0]), "r"((b)[1]))

#define LDSM_X4(r0, r1, r2, r3, addr)                                         \
    asm volatile("ldmatrix.sync.aligned.m8n8.x4.shared.b16 "                  \
                 "{%0,%1,%2,%3}, [%4];"                                       \
                 : "=r"(r0), "=r"(r1), "=r"(r2), "=r"(r3) : "r"(addr))

#define LDSM_X4_T(r0, r1, r2, r3, addr)                                       \
    asm volatile("ldmatrix.sync.aligned.m8n8.x4.trans.shared.b16 "            \
                 "{%0,%1,%2,%3}, [%4];"                                       \
                 : "=r"(r0), "=r"(r1), "=r"(r2), "=r"(r3) : "r"(addr))

#define CP_ASYNC16(dst, src)                                                  \
    asm volatile("cp.async.cg.shared.global [%0], [%1], 16;"                  \
                 :: "r"(dst), "l"(src))
#define CP_COMMIT() asm volatile("cp.async.commit_group;" ::: "memory")
#define CP_WAIT1()  asm volatile("cp.async.wait_group 1;" ::: "memory")

// ============================================================================
// Merged prep: z<3 -> activation convert (xq/xk/xv), z>=3 -> weight transpose.
// ============================================================================
__global__ void __launch_bounds__(256)
prep_kernel(const float* __restrict__ xq, const float* __restrict__ xk,
            const float* __restrict__ xv,
            const float* __restrict__ Wq, const float* __restrict__ Wk,
            const float* __restrict__ Wv, const float* __restrict__ Wo,
            __half* __restrict__ Xbase, __half* __restrict__ WTbase)
{
    const int z = blockIdx.z;
    const int tid = threadIdx.x;

    if (z < 3) {
        const float* X = (z == 0) ? xq : (z == 1) ? xk : xv;
        __half* Y = Xbase + (size_t)z * MROWS * EMB;
        size_t blk = (size_t)blockIdx.y * 32 + blockIdx.x;
        size_t i16 = blk * 256 + tid;
        const float* xp = X + i16 * 16;
        uint32_t* yp = (uint32_t*)Y + i16 * 8;
        uint32_t o[8];
#pragma unroll
        for (int q = 0; q < 4; ++q) {
            float4 v = *(const float4*)&xp[q * 4];
            o[q * 2 + 0] = h2pack(v.x, v.y);
            o[q * 2 + 1] = h2pack(v.z, v.w);
        }
        uint4 w0 = { o[0], o[1], o[2], o[3] };
        uint4 w1 = { o[4], o[5], o[6], o[7] };
        *(uint4*)&yp[0] = w0;
        *(uint4*)&yp[4] = w1;
    } else {
        const int wz = z - 3;
        const float* W = (wz == 0) ? Wq : (wz == 1) ? Wk : (wz == 2) ? Wv : Wo;
        __half* WT = WTbase + (size_t)wz * EMB * EMB;

        __shared__ float tile[32][33];
        const int tx = tid & 31;
        const int ty = tid >> 5;
        int x = blockIdx.x * 32 + tx;
        int y = blockIdx.y * 32 + ty;
#pragma unroll
        for (int j = 0; j < 32; j += 8)
            tile[ty + j][tx] = W[(size_t)(y + j) * EMB + x];
        __syncthreads();
        const int cu = tx & 15;
        const int nl0 = ty + 8 * (tx >> 4);
        uint32_t* Wu = (uint32_t*)WT;
#pragma unroll
        for (int j = 0; j < 32; j += 16) {
            int nl = nl0 + j;
            uint32_t h = h2pack(tile[2 * cu][nl], tile[2 * cu + 1][nl]);
            size_t n = (size_t)(blockIdx.x * 32 + nl);
            Wu[n * (EMB / 2) + blockIdx.y * 16 + cu] = h;
        }
    }
}

// ============================================================================
// fp16 mma.sync GEMM mainloop: 3-stage cp.async ring (depth-2 lookahead),
// ldmatrix staging, one barrier per iteration.
// ============================================================================
#define GBM 128
#define GBN 128
#define GRS 36                       // u32 per row (32 data + 4 pad)
#define TILE_U (128 * GRS)
#define GSMEM_TOTAL (6 * TILE_U * 4) // 110,592 B (3 stages x A,B)

struct GemmCtx {
    int wm, wn, g, t;
    float c[4][4][4];
};

__device__ __forceinline__ void gemm_issue_tile(
    uint32_t aDst, uint32_t bDst,
    const __half* __restrict__ Ap, const __half* __restrict__ Bp,
    uint32_t dOff, size_t gOff, size_t k0)
{
#pragma unroll
    for (int p = 0; p < 4; ++p) {
        CP_ASYNC16(aDst + dOff + (uint32_t)(32 * p * GRS * 4),
                   Ap + gOff + k0 + (size_t)32 * p * EMB);
        CP_ASYNC16(bDst + dOff + (uint32_t)(32 * p * GRS * 4),
                   Bp + gOff + k0 + (size_t)32 * p * EMB);
    }
}

__device__ __forceinline__ void gemm_mainloop(
    const __half* __restrict__ Ap, const __half* __restrict__ Bp,
    uint32_t sb, int tid, GemmCtx& ctx)
{
    const int w    = tid >> 5;
    ctx.wm = w & 1;
    ctx.wn = w >> 1;
    const int lane = tid & 31;
    ctx.g = lane >> 2;
    ctx.t = lane & 3;

    const int s  = tid & 7;
    const int r0 = tid >> 3;

    const uint32_t AsU[3] = { sb, sb + TILE_U * 4, sb + 2 * TILE_U * 4 };
    const uint32_t BsU[3] = { sb + 3 * TILE_U * 4, sb + 4 * TILE_U * 4,
                              sb + 5 * TILE_U * 4 };

#pragma unroll
    for (int mi = 0; mi < 4; ++mi)
#pragma unroll
        for (int ni = 0; ni < 4; ++ni)
#pragma unroll
            for (int j = 0; j < 4; ++j) ctx.c[mi][ni][j] = 0.f;

    const int laneRowA = ((lane & 8) ? 8 : 0) + (lane & 7);
    const int colOctA  = (lane >> 4) * 4;
    const int laneRowB = ((lane >> 4) << 3) + (lane & 7);
    const int colOctB  = (lane & 8) ? 4 : 0;

    const uint32_t dOff = (uint32_t)((r0 * GRS + s * 4) * 4);
    const size_t   gOff = (size_t)r0 * EMB + s * 8;   // halves

    // prologue: tiles 0 and 1 (one commit group each)
    gemm_issue_tile(AsU[0], BsU[0], Ap, Bp, dOff, gOff, 0);
    CP_COMMIT();
    gemm_issue_tile(AsU[1], BsU[1], Ap, Bp, dOff, gOff, 64);
    CP_COMMIT();

    const int NKT = EMB / 64;   // 16
    int cur = 0, nxt = 2;
    for (int kt = 0; kt < NKT; ++kt) {
        // commits so far = 2 + kt; tile kt done once pending <= 1
        CP_WAIT1();
        __syncthreads();   // tile kt visible; buffer nxt free (consumed kt-1)

        if (kt + 2 < NKT)
            gemm_issue_tile(AsU[nxt], BsU[nxt], Ap, Bp, dOff, gOff,
                            (size_t)(kt + 2) * 64);
        CP_COMMIT();       // always: keeps group counting exact

        const uint32_t aU = AsU[cur];
        const uint32_t bU = BsU[cur];
#pragma unroll
        for (int ks = 0; ks < 4; ++ks) {
            uint32_t af[4][4], bf[4][2];
#pragma unroll
            for (int mi = 0; mi < 4; ++mi) {
                LDSM_X4(af[mi][0], af[mi][1], af[mi][2], af[mi][3],
                        aU + (uint32_t)(((ctx.wm * 64 + mi * 16 + laneRowA) * GRS
                                         + ks * 8 + colOctA) * 4));
            }
#pragma unroll
            for (int kb = 0; kb < 2; ++kb) {
                uint32_t r0v, r1v, r2v, r3v;
                LDSM_X4(r0v, r1v, r2v, r3v,
                        bU + (uint32_t)(((ctx.wn * 32 + kb * 16 + laneRowB) * GRS
                                         + ks * 8 + colOctB) * 4));
                bf[2 * kb][0] = r0v; bf[2 * kb][1] = r1v;
                bf[2 * kb + 1][0] = r2v; bf[2 * kb + 1][1] = r3v;
            }
#pragma unroll
            for (int mi = 0; mi < 4; ++mi)
#pragma unroll
                for (int ni = 0; ni < 4; ++ni)
                    MMA_F16(ctx.c[mi][ni], af[mi], bf[ni]);
        }

        cur = (cur == 2) ? 0 : cur + 1;
        nxt = (nxt == 2) ? 0 : nxt + 1;
    }
}

// ============================================================================
// Merged QKV GEMM: outputs plain [token][dim] half (Q scaled by QSCALE).
// ============================================================================
__global__ void __launch_bounds__(256, 2)
gemm_qkv_kernel(const __half* __restrict__ Xbase, const __half* __restrict__ WTbase,
                const float* __restrict__ bq, const float* __restrict__ bk,
                const float* __restrict__ bv,
                __half* __restrict__ Qd, __half* __restrict__ Kd,
                __half* __restrict__ Vd)
{
    extern __shared__ uint32_t smu[];
    const uint32_t sb = smem_u32(smu);
    const int tid = threadIdx.x;
    const int bn = blockIdx.x * GBN;
    const int bm = blockIdx.y * GBM;
    const int z  = blockIdx.z;

    const __half* A  = Xbase  + (size_t)z * MROWS * EMB + (size_t)bm * EMB;
    const __half* Bw = WTbase + (size_t)z * EMB * EMB   + (size_t)bn * EMB;
    const float* bias = (z == 0) ? bq : (z == 1) ? bk : bv;
    __half* outp = (z == 0) ? Qd : (z == 1) ? Kd : Vd;

    GemmCtx ctx;
    gemm_mainloop(A, Bw, sb, tid, ctx);

    const int colb = bn + ctx.wn * 32;
    const int g = ctx.g, t = ctx.t;
    const float sc = (z == 0) ? QSCALE : 1.f;
    float2 bj[4];
#pragma unroll
    for (int ni = 0; ni < 4; ++ni) {
        bj[ni].x = bias[colb + ni * 8 + 2 * t];
        bj[ni].y = bias[colb + ni * 8 + 2 * t + 1];
    }

    uint32_t* Cu = (uint32_t*)outp;
#pragma unroll
    for (int mi = 0; mi < 4; ++mi) {
        const size_t row0 = (size_t)(bm + ctx.wm * 64 + mi * 16 + g);
        const size_t row1 = row0 + 8;
#pragma unroll
        for (int ni = 0; ni < 4; ++ni) {
            const int posu = (colb >> 1) + ni * 4 + t;
            Cu[row0 * (EMB / 2) + posu] =
                h2pack((ctx.c[mi][ni][0] + bj[ni].x) * sc,
                       (ctx.c[mi][ni][1] + bj[ni].y) * sc);
            Cu[row1 * (EMB / 2) + posu] =
                h2pack((ctx.c[mi][ni][2] + bj[ni].x) * sc,
                       (ctx.c[mi][ni][3] + bj[ni].y) * sc);
        }
    }
}

// ============================================================================
// Final projection GEMM: fp32 row-major output.
// ============================================================================
__global__ void __launch_bounds__(256, 2)
gemm_out_kernel(const __half* __restrict__ A, const __half* __restrict__ WT,
                const float* __restrict__ bias, float* __restrict__ C)
{
    extern __shared__ uint32_t smu[];
    const uint32_t sb = smem_u32(smu);
    const int tid = threadIdx.x;
    const int bn = blockIdx.x * GBN;
    const int bm = blockIdx.y * GBM;

    GemmCtx ctx;
    gemm_mainloop(A + (size_t)bm * EMB, WT + (size_t)bn * EMB, sb, tid, ctx);

    const int colb = bn + ctx.wn * 32;
    const int g = ctx.g, t = ctx.t;
    float2 bj[4];
#pragma unroll
    for (int ni = 0; ni < 4; ++ni) {
        bj[ni].x = bias[colb + ni * 8 + 2 * t];
        bj[ni].y = bias[colb + ni * 8 + 2 * t + 1];
    }
#pragma unroll
    for (int mi = 0; mi < 4; ++mi) {
        const size_t row0 = (size_t)(bm + ctx.wm * 64 + mi * 16 + g);
        const size_t row1 = row0 + 8;
#pragma unroll
        for (int ni = 0; ni < 4; ++ni) {
            const int col = colb + ni * 8 + 2 * t;
            float2 o0, o1;
            o0.x = ctx.c[mi][ni][0] + bj[ni].x;
            o0.y = ctx.c[mi][ni][1] + bj[ni].y;
            o1.x = ctx.c[mi][ni][2] + bj[ni].x;
            o1.y = ctx.c[mi][ni][3] + bj[ni].y;
            *(float2*)&C[row0 * EMB + col] = o0;
            *(float2*)&C[row1 * EMB + col] = o1;
        }
    }
}

// ============================================================================
// Flash attention: register-P, ldmatrix operands, 3-buffer K/V cp.async ring
// (depth-2 lookahead), one barrier per iteration. 2 CTAs/SM.
// ============================================================================
#define RS 36
#define AOFF_Q 0                              // [128][RS]
#define AOFF_K (128 * RS)                     // 3 x [64][RS]
#define AOFF_V (AOFF_K + 3 * 64 * RS)         // 3 x [64][RS]
#define ATT_SMEM ((AOFF_V + 3 * 64 * RS) * 4) // 73,728 B -> 2 CTAs/SM

__global__ void __launch_bounds__(256, 2)
attn_mma_kernel(const __half* __restrict__ Q, const __half* __restrict__ K,
                const __half* __restrict__ V, __half* __restrict__ O)
{
    extern __shared__ uint32_t smu[];
    const uint32_t sb = smem_u32(smu);

    const uint32_t QsU = sb + AOFF_Q * 4;
    const uint32_t KsU[3] = { sb + AOFF_K * 4,
                              sb + (AOFF_K + 64 * RS) * 4,
                              sb + (AOFF_K + 128 * RS) * 4 };
    const uint32_t VsU[3] = { sb + AOFF_V * 4,
                              sb + (AOFF_V + 64 * RS) * 4,
                              sb + (AOFF_V + 128 * RS) * 4 };

    const int tid = threadIdx.x;
    const int qt = blockIdx.x;           // 0..15
    const int bh = blockIdx.y;           // 0..31
    const int b  = bh >> 4;
    const int hd = bh & 15;
    const int q0 = qt * 128;

    const __half* Qg = Q + (size_t)(b * SEQ + q0) * EMB + hd * HDIM;
    const __half* Kg = K + (size_t)b * SEQ * EMB + hd * HDIM;
    const __half* Vg = V + (size_t)b * SEQ * EMB + hd * HDIM;

    const int w    = tid >> 5;
    const int lane = tid & 31;
    const int g    = lane >> 2;
    const int t    = lane & 3;
    const int rowg = 16 * w + g;

    const int cq = tid & 7;
    const int rr = tid >> 3;

    // ---- prologue: group0 = Q + K0/V0; group1 = K1/V1 ----
#pragma unroll
    for (int p = 0; p < 4; ++p) {
        int r = rr + 32 * p;
        CP_ASYNC16(QsU + (uint32_t)((r * RS + cq * 4) * 4),
                   Qg + (size_t)r * EMB + cq * 8);
    }
#pragma unroll
    for (int p = 0; p < 2; ++p) {
        int r = rr + 32 * p;
        CP_ASYNC16(KsU[0] + (uint32_t)((r * RS + cq * 4) * 4),
                   Kg + (size_t)r * EMB + cq * 8);
        CP_ASYNC16(VsU[0] + (uint32_t)((r * RS + cq * 4) * 4),
                   Vg + (size_t)r * EMB + cq * 8);
    }
    CP_COMMIT();
#pragma unroll
    for (int p = 0; p < 2; ++p) {
        int r = rr + 32 * p;
        CP_ASYNC16(KsU[1] + (uint32_t)((r * RS + cq * 4) * 4),
                   Kg + (size_t)(64 + r) * EMB + cq * 8);
        CP_ASYNC16(VsU[1] + (uint32_t)((r * RS + cq * 4) * 4),
                   Vg + (size_t)(64 + r) * EMB + cq * 8);
    }
    CP_COMMIT();

    // Q ready after group0 completes
    CP_WAIT1();
    __syncthreads();

    // ---- hoist Q a-frags via ldmatrix x4 ----
    uint32_t qf[4][4];
    {
        const int laneRowA = ((lane & 8) ? 8 : 0) + (lane & 7);
        const int colOctA  = (lane >> 4) * 4;
        const uint32_t qbase = QsU
            + (uint32_t)(((w * 16 + laneRowA) * RS + colOctA) * 4);
#pragma unroll
        for (int ks = 0; ks < 4; ++ks)
            LDSM_X4(qf[ks][0], qf[ks][1], qf[ks][2], qf[ks][3],
                    qbase + (uint32_t)(ks * 8 * 4));
    }

    float o[8][4];
#pragma unroll
    for (int ni = 0; ni < 8; ++ni)
#pragma unroll
        for (int j = 0; j < 4; ++j) o[ni][j] = 0.f;
    float lp0 = 0.f, lp1 = 0.f;

    const int laneRowB = ((lane >> 4) << 3) + (lane & 7);
    const int colOctB  = (lane & 8) ? 4 : 0;
    const uint32_t vlane = (uint32_t)(((lane & 15) * RS + 4 * (lane >> 4)) * 4);

    const int NT = SEQ / 64;   // 32
    int cur = 0, nxt = 2;
    for (int kt = 0; kt < NT; ++kt) {
        // commits = 2 + kt; tile kt done once pending <= 1
        CP_WAIT1();
        __syncthreads();

        if (kt + 2 < NT) {
            const int k0n = (kt + 2) * 64;
#pragma unroll
            for (int p = 0; p < 2; ++p) {
                int r = rr + 32 * p;
                CP_ASYNC16(KsU[nxt] + (uint32_t)((r * RS + cq * 4) * 4),
                           Kg + (size_t)(k0n + r) * EMB + cq * 8);
                CP_ASYNC16(VsU[nxt] + (uint32_t)((r * RS + cq * 4) * 4),
                           Vg + (size_t)(k0n + r) * EMB + cq * 8);
            }
        }
        CP_COMMIT();   // always

        // ---- S = Q @ K^T ----
        float s[8][4];
#pragma unroll
        for (int ni = 0; ni < 8; ++ni)
#pragma unroll
            for (int j = 0; j < 4; ++j) s[ni][j] = 0.f;

#pragma unroll
        for (int ks = 0; ks < 4; ++ks) {
#pragma unroll
            for (int kb = 0; kb < 4; ++kb) {
                uint32_t r0, r1, r2, r3;
                uint32_t a = KsU[cur]
                    + (uint32_t)(((kb * 16 + laneRowB) * RS
                                  + ks * 8 + colOctB) * 4);
                LDSM_X4(r0, r1, r2, r3, a);
                uint32_t b0[2] = { r0, r1 };
                uint32_t b1[2] = { r2, r3 };
                MMA_F16(s[2 * kb],     qf[ks], b0);
                MMA_F16(s[2 * kb + 1], qf[ks], b1);
            }
        }

        // ---- p = exp2(s) -> PV a-frags in registers ----
        uint32_t pf[4][4];
#pragma unroll
        for (int ks = 0; ks < 4; ++ks) {
            float e00 = ex2(s[2 * ks][0]);
            float e01 = ex2(s[2 * ks][1]);
            float e02 = ex2(s[2 * ks][2]);
            float e03 = ex2(s[2 * ks][3]);
            float e10 = ex2(s[2 * ks + 1][0]);
            float e11 = ex2(s[2 * ks + 1][1]);
            float e12 = ex2(s[2 * ks + 1][2]);
            float e13 = ex2(s[2 * ks + 1][3]);
            lp0 += e00 + e01 + e10 + e11;
            lp1 += e02 + e03 + e12 + e13;
            pf[ks][0] = h2pack(e00, e01);
            pf[ks][1] = h2pack(e02, e03);
            pf[ks][2] = h2pack(e10, e11);
            pf[ks][3] = h2pack(e12, e13);
        }

        // ---- O += P @ V ----
#pragma unroll
        for (int ks = 0; ks < 4; ++ks) {
            const uint32_t vrow = VsU[cur] + vlane
                                + (uint32_t)(ks * 16 * RS * 4);
#pragma unroll
            for (int d16 = 0; d16 < 4; ++d16) {
                uint32_t r0, r1, r2, r3;
                LDSM_X4_T(r0, r1, r2, r3, vrow + (uint32_t)(d16 * 8 * 4));
                uint32_t b0[2] = { r0, r1 };
                uint32_t b1[2] = { r2, r3 };
                MMA_F16(o[2 * d16],     pf[ks], b0);
                MMA_F16(o[2 * d16 + 1], pf[ks], b1);
            }
        }

        cur = (cur == 2) ? 0 : cur + 1;
        nxt = (nxt == 2) ? 0 : nxt + 1;
    }

    // ---- reduce l, normalize, store plain half2 ----
    lp0 += __shfl_xor_sync(0xffffffffu, lp0, 1);
    lp0 += __shfl_xor_sync(0xffffffffu, lp0, 2);
    lp1 += __shfl_xor_sync(0xffffffffu, lp1, 1);
    lp1 += __shfl_xor_sync(0xffffffffu, lp1, 2);
    const float inv0 = 1.f / lp0;
    const float inv1 = 1.f / lp1;

    uint32_t* Ou = (uint32_t*)O;
    const size_t tok0 = (size_t)(b * SEQ + q0 + rowg);
    const size_t tok1 = tok0 + 8;
#pragma unroll
    for (int ni = 0; ni < 8; ++ni) {
        const int posu = hd * 32 + ni * 4 + t;
        Ou[tok0 * (EMB / 2) + posu] = h2pack(o[ni][0] * inv0, o[ni][1] * inv0);
        Ou[tok1 * (EMB / 2) + posu] = h2pack(o[ni][2] * inv1, o[ni][3] * inv1);
    }
}

// ============================================================================
// launch
// ============================================================================
extern "C" void kernel_launch(void* const* d_in, const int* in_sizes, int n_in,
                              void* d_out, int out_size)
{
    const float* xv = (const float*)d_in[0];
    const float* xk = (const float*)d_in[1];
    const float* xq = (const float*)d_in[2];
    const float* Wq = (const float*)d_in[3];
    const float* bq = (const float*)d_in[4];
    const float* Wk = (const float*)d_in[5];
    const float* bk = (const float*)d_in[6];
    const float* Wv = (const float*)d_in[7];
    const float* bv = (const float*)d_in[8];
    const float* Wo = (const float*)d_in[9];
    const float* bo = (const float*)d_in[10];
    float* out = (float*)d_out;

    __half *Qd, *Kd, *Vd, *Cd, *WTd, *Xd;
    cudaGetSymbolAddress((void**)&Qd, g_Q);
    cudaGetSymbolAddress((void**)&Kd, g_K);
    cudaGetSymbolAddress((void**)&Vd, g_V);
    cudaGetSymbolAddress((void**)&Cd, g_C);
    cudaGetSymbolAddress((void**)&WTd, g_WT);
    cudaGetSymbolAddress((void**)&Xd, g_X);

    __half* WoT = WTd + 3ll * EMB * EMB;

    dim3 pgrid(32, 32, 7);
    prep_kernel<<<pgrid, 256>>>(xq, xk, xv, Wq, Wk, Wv, Wo, Xd, WTd);

    cudaFuncSetAttribute(gemm_qkv_kernel,
                         cudaFuncAttributeMaxDynamicSharedMemorySize, GSMEM_TOTAL);
    cudaFuncSetAttribute(gemm_out_kernel,
                         cudaFuncAttributeMaxDynamicSharedMemorySize, GSMEM_TOTAL);

    dim3 qkvgrid(EMB / GBN, MROWS / GBM, 3);   // (8, 32, 3)
    gemm_qkv_kernel<<<qkvgrid, 256, GSMEM_TOTAL>>>(Xd, WTd, bq, bk, bv,
                                                   Qd, Kd, Vd);

    cudaFuncSetAttribute(attn_mma_kernel,
                         cudaFuncAttributeMaxDynamicSharedMemorySize, ATT_SMEM);
    dim3 agrid(SEQ / 128, BATCH * HEADS);  // (16, 32)
    attn_mma_kernel<<<agrid, 256, ATT_SMEM>>>(Qd, Kd, Vd, Cd);

    dim3 ggrid(EMB / GBN, MROWS / GBM);   // (8, 32)
    gemm_out_kernel<<<ggrid, 256, GSMEM_TOTAL>>>(Cd, WoT, bo, out);
}

// round 16
// speedup vs baseline: 1.0407x; 1.0406x over previous
#include <cuda_runtime.h>
#include <cuda_fp16.h>
#include <cstdint>
#include <math.h>

// Problem constants
#define BATCH 2
#define SEQ   2048
#define EMB   1024
#define HEADS 16
#define HDIM  64
#define MROWS (BATCH * SEQ)   // 4096

// ---------------- scratch (device globals; no allocations allowed) ---------
__device__ __half g_Q[MROWS * EMB];     // Q proj: scaled, rounded, plain [token][dim]
__device__ __half g_K[MROWS * EMB];     // K proj: rounded, plain
__device__ __half g_V[MROWS * EMB];     // V proj: rounded, plain
__device__ __half g_C[MROWS * EMB];     // attention out: rounded, plain
__device__ __half g_WT[4][EMB * EMB];   // W^T: rounded, plain [n][k]
__device__ __half g_X[3][MROWS * EMB];  // xq/xk/xv: rounded, plain

#define QSCALE 0.18033688f   // 0.125 * log2(e)

// ============================================================================
// helpers
// ============================================================================
__device__ __forceinline__ uint32_t smem_u32(const void* p) {
    uint32_t a;
    asm("{ .reg .u64 t; cvta.to.shared.u64 t, %1; cvt.u32.u64 %0, t; }"
        : "=r"(a) : "l"(p));
    return a;
}

__device__ __forceinline__ uint32_t h2pack(float lo, float hi) {
    uint32_t r;
    asm("cvt.rn.f16x2.f32 %0, %1, %2;" : "=r"(r) : "f"(hi), "f"(lo));
    return r;
}

__device__ __forceinline__ float ex2(float x) {
    float r;
    asm("ex2.approx.f32 %0, %1;" : "=f"(r) : "f"(x));
    return r;
}

#define MMA_F16(c, a, b)                                                      \
    asm volatile("mma.sync.aligned.m16n8k16.row.col.f32.f16.f16.f32 "         \
                 "{%0,%1,%2,%3}, {%4,%5,%6,%7}, {%8,%9}, {%0,%1,%2,%3};"      \
                 : "+f"((c)[0]), "+f"((c)[1]), "+f"((c)[2]), "+f"((c)[3])     \
                 : "r"((a)[0]), "r"((a)[1]), "r"((a)[2]), "r"((a)[3]),        \
                   "r"((b)[0]), "r"((b)[1]))

#define LDSM_X4(r0, r1, r2, r3, addr)                                         \
    asm volatile("ldmatrix.sync.aligned.m8n8.x4.shared.b16 "                  \
                 "{%0,%1,%2,%3}, [%4];"                                       \
                 : "=r"(r0), "=r"(r1), "=r"(r2), "=r"(r3) : "r"(addr))

#define LDSM_X4_T(r0, r1, r2, r3, addr)                                       \
    asm volatile("ldmatrix.sync.aligned.m8n8.x4.trans.shared.b16 "            \
                 "{%0,%1,%2,%3}, [%4];"                                       \
                 : "=r"(r0), "=r"(r1), "=r"(r2), "=r"(r3) : "r"(addr))

#define CP_ASYNC16(dst, src)                                                  \
    asm volatile("cp.async.cg.shared.global [%0], [%1], 16;"                  \
                 :: "r"(dst), "l"(src))
#define CP_COMMIT() asm volatile("cp.async.commit_group;" ::: "memory")
#define CP_WAIT0()  asm volatile("cp.async.wait_group 0;" ::: "memory")
#define CP_WAIT1()  asm volatile("cp.async.wait_group 1;" ::: "memory")

// ============================================================================
// Merged prep: z<3 -> activation convert (xq/xk/xv), z>=3 -> weight transpose.
// ============================================================================
__global__ void __launch_bounds__(256)
prep_kernel(const float* __restrict__ xq, const float* __restrict__ xk,
            const float* __restrict__ xv,
            const float* __restrict__ Wq, const float* __restrict__ Wk,
            const float* __restrict__ Wv, const float* __restrict__ Wo,
            __half* __restrict__ Xbase, __half* __restrict__ WTbase)
{
    const int z = blockIdx.z;
    const int tid = threadIdx.x;

    if (z < 3) {
        const float* X = (z == 0) ? xq : (z == 1) ? xk : xv;
        __half* Y = Xbase + (size_t)z * MROWS * EMB;
        size_t blk = (size_t)blockIdx.y * 32 + blockIdx.x;
        size_t i16 = blk * 256 + tid;
        const float* xp = X + i16 * 16;
        uint32_t* yp = (uint32_t*)Y + i16 * 8;
        uint32_t o[8];
#pragma unroll
        for (int q = 0; q < 4; ++q) {
            float4 v = *(const float4*)&xp[q * 4];
            o[q * 2 + 0] = h2pack(v.x, v.y);
            o[q * 2 + 1] = h2pack(v.z, v.w);
        }
        uint4 w0 = { o[0], o[1], o[2], o[3] };
        uint4 w1 = { o[4], o[5], o[6], o[7] };
        *(uint4*)&yp[0] = w0;
        *(uint4*)&yp[4] = w1;
    } else {
        const int wz = z - 3;
        const float* W = (wz == 0) ? Wq : (wz == 1) ? Wk : (wz == 2) ? Wv : Wo;
        __half* WT = WTbase + (size_t)wz * EMB * EMB;

        __shared__ float tile[32][33];
        const int tx = tid & 31;
        const int ty = tid >> 5;
        int x = blockIdx.x * 32 + tx;
        int y = blockIdx.y * 32 + ty;
#pragma unroll
        for (int j = 0; j < 32; j += 8)
            tile[ty + j][tx] = W[(size_t)(y + j) * EMB + x];
        __syncthreads();
        const int cu = tx & 15;
        const int nl0 = ty + 8 * (tx >> 4);
        uint32_t* Wu = (uint32_t*)WT;
#pragma unroll
        for (int j = 0; j < 32; j += 16) {
            int nl = nl0 + j;
            uint32_t h = h2pack(tile[2 * cu][nl], tile[2 * cu + 1][nl]);
            size_t n = (size_t)(blockIdx.x * 32 + nl);
            Wu[n * (EMB / 2) + blockIdx.y * 16 + cu] = h;
        }
    }
}

// ============================================================================
// fp16 mma.sync GEMM mainloop: 3-stage cp.async ring, ldmatrix staging.
// ============================================================================
#define GBM 128
#define GBN 128
#define GRS 36                       // u32 per row (32 data + 4 pad)
#define TILE_U (128 * GRS)
#define GSMEM_TOTAL (6 * TILE_U * 4) // 110,592 B (3 stages x A,B)

struct GemmCtx {
    int wm, wn, g, t;
    float c[4][4][4];
};

__device__ __forceinline__ void gemm_issue_tile(
    uint32_t aDst, uint32_t bDst,
    const __half* __restrict__ Ap, const __half* __restrict__ Bp,
    uint32_t dOff, size_t gOff, size_t k0)
{
#pragma unroll
    for (int p = 0; p < 4; ++p) {
        CP_ASYNC16(aDst + dOff + (uint32_t)(32 * p * GRS * 4),
                   Ap + gOff + k0 + (size_t)32 * p * EMB);
        CP_ASYNC16(bDst + dOff + (uint32_t)(32 * p * GRS * 4),
                   Bp + gOff + k0 + (size_t)32 * p * EMB);
    }
}

__device__ __forceinline__ void gemm_mainloop(
    const __half* __restrict__ Ap, const __half* __restrict__ Bp,
    uint32_t sb, int tid, GemmCtx& ctx)
{
    const int w    = tid >> 5;
    ctx.wm = w & 1;
    ctx.wn = w >> 1;
    const int lane = tid & 31;
    ctx.g = lane >> 2;
    ctx.t = lane & 3;

    const int s  = tid & 7;
    const int r0 = tid >> 3;

    const uint32_t AsU[3] = { sb, sb + TILE_U * 4, sb + 2 * TILE_U * 4 };
    const uint32_t BsU[3] = { sb + 3 * TILE_U * 4, sb + 4 * TILE_U * 4,
                              sb + 5 * TILE_U * 4 };

#pragma unroll
    for (int mi = 0; mi < 4; ++mi)
#pragma unroll
        for (int ni = 0; ni < 4; ++ni)
#pragma unroll
            for (int j = 0; j < 4; ++j) ctx.c[mi][ni][j] = 0.f;

    const int laneRowA = ((lane & 8) ? 8 : 0) + (lane & 7);
    const int colOctA  = (lane >> 4) * 4;
    const int laneRowB = ((lane >> 4) << 3) + (lane & 7);
    const int colOctB  = (lane & 8) ? 4 : 0;

    const uint32_t dOff = (uint32_t)((r0 * GRS + s * 4) * 4);
    const size_t   gOff = (size_t)r0 * EMB + s * 8;   // halves

    gemm_issue_tile(AsU[0], BsU[0], Ap, Bp, dOff, gOff, 0);
    CP_COMMIT();
    gemm_issue_tile(AsU[1], BsU[1], Ap, Bp, dOff, gOff, 64);
    CP_COMMIT();

    const int NKT = EMB / 64;   // 16
    int cur = 0, nxt = 2;
    for (int kt = 0; kt < NKT; ++kt) {
        CP_WAIT1();
        __syncthreads();

        if (kt + 2 < NKT)
            gemm_issue_tile(AsU[nxt], BsU[nxt], Ap, Bp, dOff, gOff,
                            (size_t)(kt + 2) * 64);
        CP_COMMIT();

        const uint32_t aU = AsU[cur];
        const uint32_t bU = BsU[cur];
#pragma unroll
        for (int ks = 0; ks < 4; ++ks) {
            uint32_t af[4][4], bf[4][2];
#pragma unroll
            for (int mi = 0; mi < 4; ++mi) {
                LDSM_X4(af[mi][0], af[mi][1], af[mi][2], af[mi][3],
                        aU + (uint32_t)(((ctx.wm * 64 + mi * 16 + laneRowA) * GRS
                                         + ks * 8 + colOctA) * 4));
            }
#pragma unroll
            for (int kb = 0; kb < 2; ++kb) {
                uint32_t r0v, r1v, r2v, r3v;
                LDSM_X4(r0v, r1v, r2v, r3v,
                        bU + (uint32_t)(((ctx.wn * 32 + kb * 16 + laneRowB) * GRS
                                         + ks * 8 + colOctB) * 4));
                bf[2 * kb][0] = r0v; bf[2 * kb][1] = r1v;
                bf[2 * kb + 1][0] = r2v; bf[2 * kb + 1][1] = r3v;
            }
#pragma unroll
            for (int mi = 0; mi < 4; ++mi)
#pragma unroll
                for (int ni = 0; ni < 4; ++ni)
                    MMA_F16(ctx.c[mi][ni], af[mi], bf[ni]);
        }

        cur = (cur == 2) ? 0 : cur + 1;
        nxt = (nxt == 2) ? 0 : nxt + 1;
    }
}

// ============================================================================
// Merged QKV GEMM: outputs plain [token][dim] half (Q scaled by QSCALE).
// ============================================================================
__global__ void __launch_bounds__(256, 2)
gemm_qkv_kernel(const __half* __restrict__ Xbase, const __half* __restrict__ WTbase,
                const float* __restrict__ bq, const float* __restrict__ bk,
                const float* __restrict__ bv,
                __half* __restrict__ Qd, __half* __restrict__ Kd,
                __half* __restrict__ Vd)
{
    extern __shared__ uint32_t smu[];
    const uint32_t sb = smem_u32(smu);
    const int tid = threadIdx.x;
    const int bn = blockIdx.x * GBN;
    const int bm = blockIdx.y * GBM;
    const int z  = blockIdx.z;

    const __half* A  = Xbase  + (size_t)z * MROWS * EMB + (size_t)bm * EMB;
    const __half* Bw = WTbase + (size_t)z * EMB * EMB   + (size_t)bn * EMB;
    const float* bias = (z == 0) ? bq : (z == 1) ? bk : bv;
    __half* outp = (z == 0) ? Qd : (z == 1) ? Kd : Vd;

    GemmCtx ctx;
    gemm_mainloop(A, Bw, sb, tid, ctx);

    const int colb = bn + ctx.wn * 32;
    const int g = ctx.g, t = ctx.t;
    const float sc = (z == 0) ? QSCALE : 1.f;
    float2 bj[4];
#pragma unroll
    for (int ni = 0; ni < 4; ++ni) {
        bj[ni].x = bias[colb + ni * 8 + 2 * t];
        bj[ni].y = bias[colb + ni * 8 + 2 * t + 1];
    }

    uint32_t* Cu = (uint32_t*)outp;
#pragma unroll
    for (int mi = 0; mi < 4; ++mi) {
        const size_t row0 = (size_t)(bm + ctx.wm * 64 + mi * 16 + g);
        const size_t row1 = row0 + 8;
#pragma unroll
        for (int ni = 0; ni < 4; ++ni) {
            const int posu = (colb >> 1) + ni * 4 + t;
            Cu[row0 * (EMB / 2) + posu] =
                h2pack((ctx.c[mi][ni][0] + bj[ni].x) * sc,
                       (ctx.c[mi][ni][1] + bj[ni].y) * sc);
            Cu[row1 * (EMB / 2) + posu] =
                h2pack((ctx.c[mi][ni][2] + bj[ni].x) * sc,
                       (ctx.c[mi][ni][3] + bj[ni].y) * sc);
        }
    }
}

// ============================================================================
// Final projection GEMM: fp32 row-major output.
// ============================================================================
__global__ void __launch_bounds__(256, 2)
gemm_out_kernel(const __half* __restrict__ A, const __half* __restrict__ WT,
                const float* __restrict__ bias, float* __restrict__ C)
{
    extern __shared__ uint32_t smu[];
    const uint32_t sb = smem_u32(smu);
    const int tid = threadIdx.x;
    const int bn = blockIdx.x * GBN;
    const int bm = blockIdx.y * GBM;

    GemmCtx ctx;
    gemm_mainloop(A + (size_t)bm * EMB, WT + (size_t)bn * EMB, sb, tid, ctx);

    const int colb = bn + ctx.wn * 32;
    const int g = ctx.g, t = ctx.t;
    float2 bj[4];
#pragma unroll
    for (int ni = 0; ni < 4; ++ni) {
        bj[ni].x = bias[colb + ni * 8 + 2 * t];
        bj[ni].y = bias[colb + ni * 8 + 2 * t + 1];
    }
#pragma unroll
    for (int mi = 0; mi < 4; ++mi) {
        const size_t row0 = (size_t)(bm + ctx.wm * 64 + mi * 16 + g);
        const size_t row1 = row0 + 8;
#pragma unroll
        for (int ni = 0; ni < 4; ++ni) {
            const int col = colb + ni * 8 + 2 * t;
            float2 o0, o1;
            o0.x = ctx.c[mi][ni][0] + bj[ni].x;
            o0.y = ctx.c[mi][ni][1] + bj[ni].y;
            o1.x = ctx.c[mi][ni][2] + bj[ni].x;
            o1.y = ctx.c[mi][ni][3] + bj[ni].y;
            *(float2*)&C[row0 * EMB + col] = o0;
            *(float2*)&C[row1 * EMB + col] = o1;
        }
    }
}

// ============================================================================
// Flash attention v2: 128 threads / 64 q-rows / 4 warps (4 CTAs/SM).
// Per-warp code identical to R13: warp owns 16 rows x full 64-key width,
// register-P, ldmatrix operands, double-buffered cp.async K/V.
// ============================================================================
#define RS 36
#define AOFF_Q 0                              // [64][RS]
#define AOFF_K (64 * RS)                      // 2 x [64][RS]
#define AOFF_V (AOFF_K + 2 * 64 * RS)         // 2 x [64][RS]
#define ATT_SMEM ((AOFF_V + 2 * 64 * RS) * 4) // 46,080 B -> 4 CTAs/SM

__global__ void __launch_bounds__(128, 4)
attn_mma_kernel(const __half* __restrict__ Q, const __half* __restrict__ K,
                const __half* __restrict__ V, __half* __restrict__ O)
{
    extern __shared__ uint32_t smu[];
    const uint32_t sb = smem_u32(smu);

    const uint32_t QsU = sb + AOFF_Q * 4;
    const uint32_t KsU[2] = { sb + AOFF_K * 4, sb + (AOFF_K + 64 * RS) * 4 };
    const uint32_t VsU[2] = { sb + AOFF_V * 4, sb + (AOFF_V + 64 * RS) * 4 };

    const int tid = threadIdx.x;
    const int qt = blockIdx.x;           // 0..31
    const int bh = blockIdx.y;           // 0..31
    const int b  = bh >> 4;
    const int hd = bh & 15;
    const int q0 = qt * 64;

    const __half* Qg = Q + (size_t)(b * SEQ + q0) * EMB + hd * HDIM;
    const __half* Kg = K + (size_t)b * SEQ * EMB + hd * HDIM;
    const __half* Vg = V + (size_t)b * SEQ * EMB + hd * HDIM;

    const int w    = tid >> 5;      // 0..3 : q-rows 16w..16w+15
    const int lane = tid & 31;
    const int g    = lane >> 2;
    const int t    = lane & 3;
    const int rowg = 16 * w + g;

    const int cq = tid & 7;         // 16B chunk within 64-half row
    const int rr = tid >> 3;        // 0..15

    // ---- stage Q (64 rows), K0/V0 (64 rows each) via cp.async ----
#pragma unroll
    for (int p = 0; p < 4; ++p) {
        int r = rr + 16 * p;
        CP_ASYNC16(QsU + (uint32_t)((r * RS + cq * 4) * 4),
                   Qg + (size_t)r * EMB + cq * 8);
    }
#pragma unroll
    for (int p = 0; p < 4; ++p) {
        int r = rr + 16 * p;
        CP_ASYNC16(KsU[0] + (uint32_t)((r * RS + cq * 4) * 4),
                   Kg + (size_t)r * EMB + cq * 8);
        CP_ASYNC16(VsU[0] + (uint32_t)((r * RS + cq * 4) * 4),
                   Vg + (size_t)r * EMB + cq * 8);
    }
    CP_COMMIT();
    CP_WAIT0();
    __syncthreads();

    // ---- hoist Q a-frags via ldmatrix x4 ----
    uint32_t qf[4][4];
    {
        const int laneRowA = ((lane & 8) ? 8 : 0) + (lane & 7);
        const int colOctA  = (lane >> 4) * 4;
        const uint32_t qbase = QsU
            + (uint32_t)(((w * 16 + laneRowA) * RS + colOctA) * 4);
#pragma unroll
        for (int ks = 0; ks < 4; ++ks)
            LDSM_X4(qf[ks][0], qf[ks][1], qf[ks][2], qf[ks][3],
                    qbase + (uint32_t)(ks * 8 * 4));
    }

    float o[8][4];
#pragma unroll
    for (int ni = 0; ni < 8; ++ni)
#pragma unroll
        for (int j = 0; j < 4; ++j) o[ni][j] = 0.f;
    float lp0 = 0.f, lp1 = 0.f;

    const int laneRowB = ((lane >> 4) << 3) + (lane & 7);
    const int colOctB  = (lane & 8) ? 4 : 0;
    const uint32_t vlane = (uint32_t)(((lane & 15) * RS + 4 * (lane >> 4)) * 4);

    const int NT = SEQ / 64;   // 32
    for (int kt = 0; kt < NT; ++kt) {
        const int cur = kt & 1;

        CP_WAIT0();
        __syncthreads();

        if (kt + 1 < NT) {
            const int nxt = cur ^ 1;
            const int k0n = (kt + 1) * 64;
#pragma unroll
            for (int p = 0; p < 4; ++p) {
                int r = rr + 16 * p;
                CP_ASYNC16(KsU[nxt] + (uint32_t)((r * RS + cq * 4) * 4),
                           Kg + (size_t)(k0n + r) * EMB + cq * 8);
                CP_ASYNC16(VsU[nxt] + (uint32_t)((r * RS + cq * 4) * 4),
                           Vg + (size_t)(k0n + r) * EMB + cq * 8);
            }
            CP_COMMIT();
        }

        // ---- S = Q @ K^T ----
        float s[8][4];
#pragma unroll
        for (int ni = 0; ni < 8; ++ni)
#pragma unroll
            for (int j = 0; j < 4; ++j) s[ni][j] = 0.f;

#pragma unroll
        for (int ks = 0; ks < 4; ++ks) {
#pragma unroll
            for (int kb = 0; kb < 4; ++kb) {
                uint32_t r0, r1, r2, r3;
                uint32_t a = KsU[cur]
                    + (uint32_t)(((kb * 16 + laneRowB) * RS
                                  + ks * 8 + colOctB) * 4);
                LDSM_X4(r0, r1, r2, r3, a);
                uint32_t b0[2] = { r0, r1 };
                uint32_t b1[2] = { r2, r3 };
                MMA_F16(s[2 * kb],     qf[ks], b0);
                MMA_F16(s[2 * kb + 1], qf[ks], b1);
            }
        }

        // ---- p = exp2(s) -> PV a-frags in registers ----
        uint32_t pf[4][4];
#pragma unroll
        for (int ks = 0; ks < 4; ++ks) {
            float e00 = ex2(s[2 * ks][0]);
            float e01 = ex2(s[2 * ks][1]);
            float e02 = ex2(s[2 * ks][2]);
            float e03 = ex2(s[2 * ks][3]);
            float e10 = ex2(s[2 * ks + 1][0]);
            float e11 = ex2(s[2 * ks + 1][1]);
            float e12 = ex2(s[2 * ks + 1][2]);
            float e13 = ex2(s[2 * ks + 1][3]);
            lp0 += e00 + e01 + e10 + e11;
            lp1 += e02 + e03 + e12 + e13;
            pf[ks][0] = h2pack(e00, e01);
            pf[ks][1] = h2pack(e02, e03);
            pf[ks][2] = h2pack(e10, e11);
            pf[ks][3] = h2pack(e12, e13);
        }

        // ---- O += P @ V ----
#pragma unroll
        for (int ks = 0; ks < 4; ++ks) {
            const uint32_t vrow = VsU[cur] + vlane
                                + (uint32_t)(ks * 16 * RS * 4);
#pragma unroll
            for (int d16 = 0; d16 < 4; ++d16) {
                uint32_t r0, r1, r2, r3;
                LDSM_X4_T(r0, r1, r2, r3, vrow + (uint32_t)(d16 * 8 * 4));
                uint32_t b0[2] = { r0, r1 };
                uint32_t b1[2] = { r2, r3 };
                MMA_F16(o[2 * d16],     pf[ks], b0);
                MMA_F16(o[2 * d16 + 1], pf[ks], b1);
            }
        }
    }

    // ---- reduce l, normalize, store plain half2 ----
    lp0 += __shfl_xor_sync(0xffffffffu, lp0, 1);
    lp0 += __shfl_xor_sync(0xffffffffu, lp0, 2);
    lp1 += __shfl_xor_sync(0xffffffffu, lp1, 1);
    lp1 += __shfl_xor_sync(0xffffffffu, lp1, 2);
    const float inv0 = 1.f / lp0;
    const float inv1 = 1.f / lp1;

    uint32_t* Ou = (uint32_t*)O;
    const size_t tok0 = (size_t)(b * SEQ + q0 + rowg);
    const size_t tok1 = tok0 + 8;
#pragma unroll
    for (int ni = 0; ni < 8; ++ni) {
        const int posu = hd * 32 + ni * 4 + t;
        Ou[tok0 * (EMB / 2) + posu] = h2pack(o[ni][0] * inv0, o[ni][1] * inv0);
        Ou[tok1 * (EMB / 2) + posu] = h2pack(o[ni][2] * inv1, o[ni][3] * inv1);
    }
}

// ============================================================================
// launch
// ============================================================================
extern "C" void kernel_launch(void* const* d_in, const int* in_sizes, int n_in,
                              void* d_out, int out_size)
{
    const float* xv = (const float*)d_in[0];
    const float* xk = (const float*)d_in[1];
    const float* xq = (const float*)d_in[2];
    const float* Wq = (const float*)d_in[3];
    const float* bq = (const float*)d_in[4];
    const float* Wk = (const float*)d_in[5];
    const float* bk = (const float*)d_in[6];
    const float* Wv = (const float*)d_in[7];
    const float* bv = (const float*)d_in[8];
    const float* Wo = (const float*)d_in[9];
    const float* bo = (const float*)d_in[10];
    float* out = (float*)d_out;

    __half *Qd, *Kd, *Vd, *Cd, *WTd, *Xd;
    cudaGetSymbolAddress((void**)&Qd, g_Q);
    cudaGetSymbolAddress((void**)&Kd, g_K);
    cudaGetSymbolAddress((void**)&Vd, g_V);
    cudaGetSymbolAddress((void**)&Cd, g_C);
    cudaGetSymbolAddress((void**)&WTd, g_WT);
    cudaGetSymbolAddress((void**)&Xd, g_X);

    __half* WoT = WTd + 3ll * EMB * EMB;

    dim3 pgrid(32, 32, 7);
    prep_kernel<<<pgrid, 256>>>(xq, xk, xv, Wq, Wk, Wv, Wo, Xd, WTd);

    cudaFuncSetAttribute(gemm_qkv_kernel,
                         cudaFuncAttributeMaxDynamicSharedMemorySize, GSMEM_TOTAL);
    cudaFuncSetAttribute(gemm_out_kernel,
                         cudaFuncAttributeMaxDynamicSharedMemorySize, GSMEM_TOTAL);

    dim3 qkvgrid(EMB / GBN, MROWS / GBM, 3);   // (8, 32, 3)
    gemm_qkv_kernel<<<qkvgrid, 256, GSMEM_TOTAL>>>(Xd, WTd, bq, bk, bv,
                                                   Qd, Kd, Vd);

    cudaFuncSetAttribute(attn_mma_kernel,
                         cudaFuncAttributeMaxDynamicSharedMemorySize, ATT_SMEM);
    dim3 agrid(SEQ / 64, BATCH * HEADS);  // (32, 32)
    attn_mma_kernel<<<agrid, 128, ATT_SMEM>>>(Qd, Kd, Vd, Cd);

    dim3 ggrid(EMB / GBN, MROWS / GBM);   // (8, 32)
    gemm_out_kernel<<<ggrid, 256, GSMEM_TOTAL>>>(Cd, WoT, bo, out);
}

// round 17
// speedup vs baseline: 1.0628x; 1.0212x over previous
#include <cuda_runtime.h>
#include <cuda_fp16.h>
#include <cstdint>
#include <math.h>

// Problem constants
#define BATCH 2
#define SEQ   2048
#define EMB   1024
#define HEADS 16
#define HDIM  64
#define MROWS (BATCH * SEQ)   // 4096

// ---------------- scratch (device globals; no allocations allowed) ---------
__device__ __half g_Q[MROWS * EMB];     // Q proj: scaled, rounded, plain [token][dim]
__device__ __half g_K[MROWS * EMB];     // K proj: rounded, plain
__device__ __half g_V[MROWS * EMB];     // V proj: rounded, plain
__device__ __half g_C[MROWS * EMB];     // attention out: rounded, plain
__device__ __half g_WT[4][EMB * EMB];   // W^T: rounded, plain [n][k]
__device__ __half g_X[3][MROWS * EMB];  // xq/xk/xv: rounded, plain

#define QSCALE 0.18033688f   // 0.125 * log2(e)

// ============================================================================
// helpers
// ============================================================================
__device__ __forceinline__ uint32_t smem_u32(const void* p) {
    uint32_t a;
    asm("{ .reg .u64 t; cvta.to.shared.u64 t, %1; cvt.u32.u64 %0, t; }"
        : "=r"(a) : "l"(p));
    return a;
}

__device__ __forceinline__ uint32_t h2pack(float lo, float hi) {
    uint32_t r;
    asm("cvt.rn.f16x2.f32 %0, %1, %2;" : "=r"(r) : "f"(hi), "f"(lo));
    return r;
}

__device__ __forceinline__ float ex2(float x) {
    float r;
    asm("ex2.approx.f32 %0, %1;" : "=f"(r) : "f"(x));
    return r;
}

#define MMA_F16(c, a, b)                                                      \
    asm volatile("mma.sync.aligned.m16n8k16.row.col.f32.f16.f16.f32 "         \
                 "{%0,%1,%2,%3}, {%4,%5,%6,%7}, {%8,%9}, {%0,%1,%2,%3};"      \
                 : "+f"((c)[0]), "+f"((c)[1]), "+f"((c)[2]), "+f"((c)[3])     \
                 : "r"((a)[0]), "r"((a)[1]), "r"((a)[2]), "r"((a)[3]),        \
                   "r"((b)[0]), "r"((b)[1]))

#define LDSM_X4(r0, r1, r2, r3, addr)                                         \
    asm volatile("ldmatrix.sync.aligned.m8n8.x4.shared.b16 "                  \
                 "{%0,%1,%2,%3}, [%4];"                                       \
                 : "=r"(r0), "=r"(r1), "=r"(r2), "=r"(r3) : "r"(addr))

#define LDSM_X4_T(r0, r1, r2, r3, addr)                                       \
    asm volatile("ldmatrix.sync.aligned.m8n8.x4.trans.shared.b16 "            \
                 "{%0,%1,%2,%3}, [%4];"                                       \
                 : "=r"(r0), "=r"(r1), "=r"(r2), "=r"(r3) : "r"(addr))

#define CP_ASYNC16(dst, src)                                                  \
    asm volatile("cp.async.cg.shared.global [%0], [%1], 16;"                  \
                 :: "r"(dst), "l"(src))
#define CP_COMMIT() asm volatile("cp.async.commit_group;" ::: "memory")
#define CP_WAIT0()  asm volatile("cp.async.wait_group 0;" ::: "memory")
#define CP_WAIT1()  asm volatile("cp.async.wait_group 1;" ::: "memory")

// ============================================================================
// Merged prep: z<3 -> activation convert (xq/xk/xv), z>=3 -> weight transpose.
// ============================================================================
__global__ void __launch_bounds__(256)
prep_kernel(const float* __restrict__ xq, const float* __restrict__ xk,
            const float* __restrict__ xv,
            const float* __restrict__ Wq, const float* __restrict__ Wk,
            const float* __restrict__ Wv, const float* __restrict__ Wo,
            __half* __restrict__ Xbase, __half* __restrict__ WTbase)
{
    const int z = blockIdx.z;
    const int tid = threadIdx.x;

    if (z < 3) {
        const float* X = (z == 0) ? xq : (z == 1) ? xk : xv;
        __half* Y = Xbase + (size_t)z * MROWS * EMB;
        size_t blk = (size_t)blockIdx.y * 32 + blockIdx.x;
        size_t i16 = blk * 256 + tid;
        const float* xp = X + i16 * 16;
        uint32_t* yp = (uint32_t*)Y + i16 * 8;
        uint32_t o[8];
#pragma unroll
        for (int q = 0; q < 4; ++q) {
            float4 v = *(const float4*)&xp[q * 4];
            o[q * 2 + 0] = h2pack(v.x, v.y);
            o[q * 2 + 1] = h2pack(v.z, v.w);
        }
        uint4 w0 = { o[0], o[1], o[2], o[3] };
        uint4 w1 = { o[4], o[5], o[6], o[7] };
        *(uint4*)&yp[0] = w0;
        *(uint4*)&yp[4] = w1;
    } else {
        const int wz = z - 3;
        const float* W = (wz == 0) ? Wq : (wz == 1) ? Wk : (wz == 2) ? Wv : Wo;
        __half* WT = WTbase + (size_t)wz * EMB * EMB;

        __shared__ float tile[32][33];
        const int tx = tid & 31;
        const int ty = tid >> 5;
        int x = blockIdx.x * 32 + tx;
        int y = blockIdx.y * 32 + ty;
#pragma unroll
        for (int j = 0; j < 32; j += 8)
            tile[ty + j][tx] = W[(size_t)(y + j) * EMB + x];
        __syncthreads();
        const int cu = tx & 15;
        const int nl0 = ty + 8 * (tx >> 4);
        uint32_t* Wu = (uint32_t*)WT;
#pragma unroll
        for (int j = 0; j < 32; j += 16) {
            int nl = nl0 + j;
            uint32_t h = h2pack(tile[2 * cu][nl], tile[2 * cu + 1][nl]);
            size_t n = (size_t)(blockIdx.x * 32 + nl);
            Wu[n * (EMB / 2) + blockIdx.y * 16 + cu] = h;
        }
    }
}

// ============================================================================
// fp16 mma.sync GEMM mainloop: 128 threads, tile 64x128 (4 warps = 1M x 4N),
// 2-stage cp.async ring, ldmatrix staging. 4 CTAs/SM.
// ============================================================================
#define GBM 64
#define GBN 128
#define GRS 36                       // u32 per row (32 data + 4 pad)
#define ATILE_U (64 * GRS)
#define BTILE_U (128 * GRS)
#define STAGE_U (ATILE_U + BTILE_U)
#define GSMEM_TOTAL (2 * STAGE_U * 4)   // 55,296 B

struct GemmCtx {
    int wn, g, t;
    float c[4][4][4];
};

__device__ __forceinline__ void gemm_issue_tile(
    uint32_t aDst, uint32_t bDst,
    const __half* __restrict__ Ap, const __half* __restrict__ Bp,
    uint32_t dOff, size_t gOff, size_t k0)
{
    // 128 threads: A = 64 rows (4 per thread-row-group), B = 128 rows (8)
#pragma unroll
    for (int p = 0; p < 4; ++p) {
        CP_ASYNC16(aDst + dOff + (uint32_t)(16 * p * GRS * 4),
                   Ap + gOff + k0 + (size_t)16 * p * EMB);
    }
#pragma unroll
    for (int p = 0; p < 8; ++p) {
        CP_ASYNC16(bDst + dOff + (uint32_t)(16 * p * GRS * 4),
                   Bp + gOff + k0 + (size_t)16 * p * EMB);
    }
}

__device__ __forceinline__ void gemm_mainloop(
    const __half* __restrict__ Ap, const __half* __restrict__ Bp,
    uint32_t sb, int tid, GemmCtx& ctx)
{
    ctx.wn = tid >> 5;              // 0..3
    const int lane = tid & 31;
    ctx.g = lane >> 2;
    ctx.t = lane & 3;

    const int s  = tid & 7;         // 16B chunk within 64-half row
    const int r0 = tid >> 3;        // 0..15

    const uint32_t AsU[2] = { sb,                   sb + STAGE_U * 4 };
    const uint32_t BsU[2] = { sb + ATILE_U * 4,     sb + (STAGE_U + ATILE_U) * 4 };

#pragma unroll
    for (int mi = 0; mi < 4; ++mi)
#pragma unroll
        for (int ni = 0; ni < 4; ++ni)
#pragma unroll
            for (int j = 0; j < 4; ++j) ctx.c[mi][ni][j] = 0.f;

    const int laneRowA = ((lane & 8) ? 8 : 0) + (lane & 7);
    const int colOctA  = (lane >> 4) * 4;
    const int laneRowB = ((lane >> 4) << 3) + (lane & 7);
    const int colOctB  = (lane & 8) ? 4 : 0;

    const uint32_t dOff = (uint32_t)((r0 * GRS + s * 4) * 4);
    const size_t   gOff = (size_t)r0 * EMB + s * 8;   // halves

    gemm_issue_tile(AsU[0], BsU[0], Ap, Bp, dOff, gOff, 0);
    CP_COMMIT();

    const int NKT = EMB / 64;   // 16
    for (int kt = 0; kt < NKT; ++kt) {
        const int b = kt & 1;

        if (kt + 1 < NKT) {
            const int nb = b ^ 1;
            gemm_issue_tile(AsU[nb], BsU[nb], Ap, Bp, dOff, gOff,
                            (size_t)(kt + 1) * 64);
            CP_COMMIT();
            CP_WAIT1();
        } else {
            CP_WAIT0();
        }
        __syncthreads();

        const uint32_t aU = AsU[b];
        const uint32_t bU = BsU[b];
#pragma unroll
        for (int ks = 0; ks < 4; ++ks) {
            uint32_t af[4][4], bf[4][2];
#pragma unroll
            for (int mi = 0; mi < 4; ++mi) {
                LDSM_X4(af[mi][0], af[mi][1], af[mi][2], af[mi][3],
                        aU + (uint32_t)(((mi * 16 + laneRowA) * GRS
                                         + ks * 8 + colOctA) * 4));
            }
#pragma unroll
            for (int kb = 0; kb < 2; ++kb) {
                uint32_t r0v, r1v, r2v, r3v;
                LDSM_X4(r0v, r1v, r2v, r3v,
                        bU + (uint32_t)(((ctx.wn * 32 + kb * 16 + laneRowB) * GRS
                                         + ks * 8 + colOctB) * 4));
                bf[2 * kb][0] = r0v; bf[2 * kb][1] = r1v;
                bf[2 * kb + 1][0] = r2v; bf[2 * kb + 1][1] = r3v;
            }
#pragma unroll
            for (int mi = 0; mi < 4; ++mi)
#pragma unroll
                for (int ni = 0; ni < 4; ++ni)
                    MMA_F16(ctx.c[mi][ni], af[mi], bf[ni]);
        }
        __syncthreads();
    }
}

// ============================================================================
// Merged QKV GEMM: outputs plain [token][dim] half (Q scaled by QSCALE).
// ============================================================================
__global__ void __launch_bounds__(128, 4)
gemm_qkv_kernel(const __half* __restrict__ Xbase, const __half* __restrict__ WTbase,
                const float* __restrict__ bq, const float* __restrict__ bk,
                const float* __restrict__ bv,
                __half* __restrict__ Qd, __half* __restrict__ Kd,
                __half* __restrict__ Vd)
{
    extern __shared__ uint32_t smu[];
    const uint32_t sb = smem_u32(smu);
    const int tid = threadIdx.x;
    const int bn = blockIdx.x * GBN;
    const int bm = blockIdx.y * GBM;
    const int z  = blockIdx.z;

    const __half* A  = Xbase  + (size_t)z * MROWS * EMB + (size_t)bm * EMB;
    const __half* Bw = WTbase + (size_t)z * EMB * EMB   + (size_t)bn * EMB;
    const float* bias = (z == 0) ? bq : (z == 1) ? bk : bv;
    __half* outp = (z == 0) ? Qd : (z == 1) ? Kd : Vd;

    GemmCtx ctx;
    gemm_mainloop(A, Bw, sb, tid, ctx);

    const int colb = bn + ctx.wn * 32;
    const int g = ctx.g, t = ctx.t;
    const float sc = (z == 0) ? QSCALE : 1.f;
    float2 bj[4];
#pragma unroll
    for (int ni = 0; ni < 4; ++ni) {
        bj[ni].x = bias[colb + ni * 8 + 2 * t];
        bj[ni].y = bias[colb + ni * 8 + 2 * t + 1];
    }

    uint32_t* Cu = (uint32_t*)outp;
#pragma unroll
    for (int mi = 0; mi < 4; ++mi) {
        const size_t row0 = (size_t)(bm + mi * 16 + g);
        const size_t row1 = row0 + 8;
#pragma unroll
        for (int ni = 0; ni < 4; ++ni) {
            const int posu = (colb >> 1) + ni * 4 + t;
            Cu[row0 * (EMB / 2) + posu] =
                h2pack((ctx.c[mi][ni][0] + bj[ni].x) * sc,
                       (ctx.c[mi][ni][1] + bj[ni].y) * sc);
            Cu[row1 * (EMB / 2) + posu] =
                h2pack((ctx.c[mi][ni][2] + bj[ni].x) * sc,
                       (ctx.c[mi][ni][3] + bj[ni].y) * sc);
        }
    }
}

// ============================================================================
// Final projection GEMM: fp32 row-major output.
// ============================================================================
__global__ void __launch_bounds__(128, 4)
gemm_out_kernel(const __half* __restrict__ A, const __half* __restrict__ WT,
                const float* __restrict__ bias, float* __restrict__ C)
{
    extern __shared__ uint32_t smu[];
    const uint32_t sb = smem_u32(smu);
    const int tid = threadIdx.x;
    const int bn = blockIdx.x * GBN;
    const int bm = blockIdx.y * GBM;

    GemmCtx ctx;
    gemm_mainloop(A + (size_t)bm * EMB, WT + (size_t)bn * EMB, sb, tid, ctx);

    const int colb = bn + ctx.wn * 32;
    const int g = ctx.g, t = ctx.t;
    float2 bj[4];
#pragma unroll
    for (int ni = 0; ni < 4; ++ni) {
        bj[ni].x = bias[colb + ni * 8 + 2 * t];
        bj[ni].y = bias[colb + ni * 8 + 2 * t + 1];
    }
#pragma unroll
    for (int mi = 0; mi < 4; ++mi) {
        const size_t row0 = (size_t)(bm + mi * 16 + g);
        const size_t row1 = row0 + 8;
#pragma unroll
        for (int ni = 0; ni < 4; ++ni) {
            const int col = colb + ni * 8 + 2 * t;
            float2 o0, o1;
            o0.x = ctx.c[mi][ni][0] + bj[ni].x;
            o0.y = ctx.c[mi][ni][1] + bj[ni].y;
            o1.x = ctx.c[mi][ni][2] + bj[ni].x;
            o1.y = ctx.c[mi][ni][3] + bj[ni].y;
            *(float2*)&C[row0 * EMB + col] = o0;
            *(float2*)&C[row1 * EMB + col] = o1;
        }
    }
}

// ============================================================================
// Flash attention (unchanged from R16): 128 threads / 64 q-rows / 4 warps,
// register-P, ldmatrix operands, double-buffered cp.async K/V. 4 CTAs/SM.
// ============================================================================
#define RS 36
#define AOFF_Q 0                              // [64][RS]
#define AOFF_K (64 * RS)                      // 2 x [64][RS]
#define AOFF_V (AOFF_K + 2 * 64 * RS)         // 2 x [64][RS]
#define ATT_SMEM ((AOFF_V + 2 * 64 * RS) * 4) // 46,080 B -> 4 CTAs/SM

__global__ void __launch_bounds__(128, 4)
attn_mma_kernel(const __half* __restrict__ Q, const __half* __restrict__ K,
                const __half* __restrict__ V, __half* __restrict__ O)
{
    extern __shared__ uint32_t smu[];
    const uint32_t sb = smem_u32(smu);

    const uint32_t QsU = sb + AOFF_Q * 4;
    const uint32_t KsU[2] = { sb + AOFF_K * 4, sb + (AOFF_K + 64 * RS) * 4 };
    const uint32_t VsU[2] = { sb + AOFF_V * 4, sb + (AOFF_V + 64 * RS) * 4 };

    const int tid = threadIdx.x;
    const int qt = blockIdx.x;           // 0..31
    const int bh = blockIdx.y;           // 0..31
    const int b  = bh >> 4;
    const int hd = bh & 15;
    const int q0 = qt * 64;

    const __half* Qg = Q + (size_t)(b * SEQ + q0) * EMB + hd * HDIM;
    const __half* Kg = K + (size_t)b * SEQ * EMB + hd * HDIM;
    const __half* Vg = V + (size_t)b * SEQ * EMB + hd * HDIM;

    const int w    = tid >> 5;      // 0..3 : q-rows 16w..16w+15
    const int lane = tid & 31;
    const int g    = lane >> 2;
    const int t    = lane & 3;
    const int rowg = 16 * w + g;

    const int cq = tid & 7;
    const int rr = tid >> 3;        // 0..15

    // ---- stage Q (64 rows), K0/V0 (64 rows each) via cp.async ----
#pragma unroll
    for (int p = 0; p < 4; ++p) {
        int r = rr + 16 * p;
        CP_ASYNC16(QsU + (uint32_t)((r * RS + cq * 4) * 4),
                   Qg + (size_t)r * EMB + cq * 8);
    }
#pragma unroll
    for (int p = 0; p < 4; ++p) {
        int r = rr + 16 * p;
        CP_ASYNC16(KsU[0] + (uint32_t)((r * RS + cq * 4) * 4),
                   Kg + (size_t)r * EMB + cq * 8);
        CP_ASYNC16(VsU[0] + (uint32_t)((r * RS + cq * 4) * 4),
                   Vg + (size_t)r * EMB + cq * 8);
    }
    CP_COMMIT();
    CP_WAIT0();
    __syncthreads();

    // ---- hoist Q a-frags via ldmatrix x4 ----
    uint32_t qf[4][4];
    {
        const int laneRowA = ((lane & 8) ? 8 : 0) + (lane & 7);
        const int colOctA  = (lane >> 4) * 4;
        const uint32_t qbase = QsU
            + (uint32_t)(((w * 16 + laneRowA) * RS + colOctA) * 4);
#pragma unroll
        for (int ks = 0; ks < 4; ++ks)
            LDSM_X4(qf[ks][0], qf[ks][1], qf[ks][2], qf[ks][3],
                    qbase + (uint32_t)(ks * 8 * 4));
    }

    float o[8][4];
#pragma unroll
    for (int ni = 0; ni < 8; ++ni)
#pragma unroll
        for (int j = 0; j < 4; ++j) o[ni][j] = 0.f;
    float lp0 = 0.f, lp1 = 0.f;

    const int laneRowB = ((lane >> 4) << 3) + (lane & 7);
    const int colOctB  = (lane & 8) ? 4 : 0;
    const uint32_t vlane = (uint32_t)(((lane & 15) * RS + 4 * (lane >> 4)) * 4);

    const int NT = SEQ / 64;   // 32
    for (int kt = 0; kt < NT; ++kt) {
        const int cur = kt & 1;

        CP_WAIT0();
        __syncthreads();

        if (kt + 1 < NT) {
            const int nxt = cur ^ 1;
            const int k0n = (kt + 1) * 64;
#pragma unroll
            for (int p = 0; p < 4; ++p) {
                int r = rr + 16 * p;
                CP_ASYNC16(KsU[nxt] + (uint32_t)((r * RS + cq * 4) * 4),
                           Kg + (size_t)(k0n + r) * EMB + cq * 8);
                CP_ASYNC16(VsU[nxt] + (uint32_t)((r * RS + cq * 4) * 4),
                           Vg + (size_t)(k0n + r) * EMB + cq * 8);
            }
            CP_COMMIT();
        }

        // ---- S = Q @ K^T ----
        float s[8][4];
#pragma unroll
        for (int ni = 0; ni < 8; ++ni)
#pragma unroll
            for (int j = 0; j < 4; ++j) s[ni][j] = 0.f;

#pragma unroll
        for (int ks = 0; ks < 4; ++ks) {
#pragma unroll
            for (int kb = 0; kb < 4; ++kb) {
                uint32_t r0, r1, r2, r3;
                uint32_t a = KsU[cur]
                    + (uint32_t)(((kb * 16 + laneRowB) * RS
                                  + ks * 8 + colOctB) * 4);
                LDSM_X4(r0, r1, r2, r3, a);
                uint32_t b0[2] = { r0, r1 };
                uint32_t b1[2] = { r2, r3 };
                MMA_F16(s[2 * kb],     qf[ks], b0);
                MMA_F16(s[2 * kb + 1], qf[ks], b1);
            }
        }

        // ---- p = exp2(s) -> PV a-frags in registers ----
        uint32_t pf[4][4];
#pragma unroll
        for (int ks = 0; ks < 4; ++ks) {
            float e00 = ex2(s[2 * ks][0]);
            float e01 = ex2(s[2 * ks][1]);
            float e02 = ex2(s[2 * ks][2]);
            float e03 = ex2(s[2 * ks][3]);
            float e10 = ex2(s[2 * ks + 1][0]);
            float e11 = ex2(s[2 * ks + 1][1]);
            float e12 = ex2(s[2 * ks + 1][2]);
            float e13 = ex2(s[2 * ks + 1][3]);
            lp0 += e00 + e01 + e10 + e11;
            lp1 += e02 + e03 + e12 + e13;
            pf[ks][0] = h2pack(e00, e01);
            pf[ks][1] = h2pack(e02, e03);
            pf[ks][2] = h2pack(e10, e11);
            pf[ks][3] = h2pack(e12, e13);
        }

        // ---- O += P @ V ----
#pragma unroll
        for (int ks = 0; ks < 4; ++ks) {
            const uint32_t vrow = VsU[cur] + vlane
                                + (uint32_t)(ks * 16 * RS * 4);
#pragma unroll
            for (int d16 = 0; d16 < 4; ++d16) {
                uint32_t r0, r1, r2, r3;
                LDSM_X4_T(r0, r1, r2, r3, vrow + (uint32_t)(d16 * 8 * 4));
                uint32_t b0[2] = { r0, r1 };
                uint32_t b1[2] = { r2, r3 };
                MMA_F16(o[2 * d16],     pf[ks], b0);
                MMA_F16(o[2 * d16 + 1], pf[ks], b1);
            }
        }
    }

    // ---- reduce l, normalize, store plain half2 ----
    lp0 += __shfl_xor_sync(0xffffffffu, lp0, 1);
    lp0 += __shfl_xor_sync(0xffffffffu, lp0, 2);
    lp1 += __shfl_xor_sync(0xffffffffu, lp1, 1);
    lp1 += __shfl_xor_sync(0xffffffffu, lp1, 2);
    const float inv0 = 1.f / lp0;
    const float inv1 = 1.f / lp1;

    uint32_t* Ou = (uint32_t*)O;
    const size_t tok0 = (size_t)(b * SEQ + q0 + rowg);
    const size_t tok1 = tok0 + 8;
#pragma unroll
    for (int ni = 0; ni < 8; ++ni) {
        const int posu = hd * 32 + ni * 4 + t;
        Ou[tok0 * (EMB / 2) + posu] = h2pack(o[ni][0] * inv0, o[ni][1] * inv0);
        Ou[tok1 * (EMB / 2) + posu] = h2pack(o[ni][2] * inv1, o[ni][3] * inv1);
    }
}

// ============================================================================
// launch
// ============================================================================
extern "C" void kernel_launch(void* const* d_in, const int* in_sizes, int n_in,
                              void* d_out, int out_size)
{
    const float* xv = (const float*)d_in[0];
    const float* xk = (const float*)d_in[1];
    const float* xq = (const float*)d_in[2];
    const float* Wq = (const float*)d_in[3];
    const float* bq = (const float*)d_in[4];
    const float* Wk = (const float*)d_in[5];
    const float* bk = (const float*)d_in[6];
    const float* Wv = (const float*)d_in[7];
    const float* bv = (const float*)d_in[8];
    const float* Wo = (const float*)d_in[9];
    const float* bo = (const float*)d_in[10];
    float* out = (float*)d_out;

    __half *Qd, *Kd, *Vd, *Cd, *WTd, *Xd;
    cudaGetSymbolAddress((void**)&Qd, g_Q);
    cudaGetSymbolAddress((void**)&Kd, g_K);
    cudaGetSymbolAddress((void**)&Vd, g_V);
    cudaGetSymbolAddress((void**)&Cd, g_C);
    cudaGetSymbolAddress((void**)&WTd, g_WT);
    cudaGetSymbolAddress((void**)&Xd, g_X);

    __half* WoT = WTd + 3ll * EMB * EMB;

    dim3 pgrid(32, 32, 7);
    prep_kernel<<<pgrid, 256>>>(xq, xk, xv, Wq, Wk, Wv, Wo, Xd, WTd);

    cudaFuncSetAttribute(gemm_qkv_kernel,
                         cudaFuncAttributeMaxDynamicSharedMemorySize, GSMEM_TOTAL);
    cudaFuncSetAttribute(gemm_out_kernel,
                         cudaFuncAttributeMaxDynamicSharedMemorySize, GSMEM_TOTAL);

    dim3 qkvgrid(EMB / GBN, MROWS / GBM, 3);   // (8, 64, 3)
    gemm_qkv_kernel<<<qkvgrid, 128, GSMEM_TOTAL>>>(Xd, WTd, bq, bk, bv,
                                                   Qd, Kd, Vd);

    cudaFuncSetAttribute(attn_mma_kernel,
                         cudaFuncAttributeMaxDynamicSharedMemorySize, ATT_SMEM);
    dim3 agrid(SEQ / 64, BATCH * HEADS);  // (32, 32)
    attn_mma_kernel<<<agrid, 128, ATT_SMEM>>>(Qd, Kd, Vd, Cd);

    dim3 ggrid(EMB / GBN, MROWS / GBM);   // (8, 64)
    gemm_out_kernel<<<ggrid, 128, GSMEM_TOTAL>>>(Cd, WoT, bo, out);
}